// round 5
// baseline (speedup 1.0000x reference)
#include <cuda_runtime.h>
#include <cuda_bf16.h>
#include <math.h>
#include <stdint.h>

// ---------------- problem constants ----------------
#define TOK     2048
#define HDIM    1024
#define FDIM    512
#define F2DIM   1024
#define NEXP    64
#define TOPK    8
#define NGRP    8
#define TGRP    4
#define CAPE    1024
#define SKTOT   (TOK*TOPK)
#define SCALE   2.5f

// ---------------- device scratch: bf16 hi/lo planes ----------------
__device__ __nv_bfloat16 g_w1h[NEXP * FDIM * HDIM];
__device__ __nv_bfloat16 g_w1l[NEXP * FDIM * HDIM];
__device__ __nv_bfloat16 g_w3h[NEXP * FDIM * HDIM];
__device__ __nv_bfloat16 g_w3l[NEXP * FDIM * HDIM];
__device__ __nv_bfloat16 g_w2h[NEXP * HDIM * FDIM];
__device__ __nv_bfloat16 g_w2l[NEXP * HDIM * FDIM];
__device__ __nv_bfloat16 g_sgh[F2DIM * HDIM];
__device__ __nv_bfloat16 g_sgl[F2DIM * HDIM];
__device__ __nv_bfloat16 g_suh[F2DIM * HDIM];
__device__ __nv_bfloat16 g_sul[F2DIM * HDIM];
__device__ __nv_bfloat16 g_sdh[HDIM * F2DIM];
__device__ __nv_bfloat16 g_sdl[HDIM * F2DIM];
__device__ __nv_bfloat16 g_xh[TOK * HDIM];
__device__ __nv_bfloat16 g_xl[TOK * HDIM];
__device__ __nv_bfloat16 g_hbuf_hi[SKTOT * FDIM];
__device__ __nv_bfloat16 g_hbuf_lo[SKTOT * FDIM];
__device__ __nv_bfloat16 g_hs_hi[TOK * F2DIM];
__device__ __nv_bfloat16 g_hs_lo[TOK * F2DIM];
__device__ int   g_topk_idx[SKTOT];
__device__ float g_topk_w[SKTOT];
__device__ int   g_counts[NEXP];
__device__ int   g_fill[NEXP];
__device__ int   g_offsets[NEXP];
__device__ int   g_ecount[NEXP];
__device__ int   g_row_token[SKTOT];
__device__ float g_row_weight[SKTOT];

// ---------------- helpers ----------------
__device__ __forceinline__ float silu_mul(float g, float u) {
    return g / (1.f + expf(-g)) * u;
}
__device__ __forceinline__ uint32_t smem_u32(const void* p) {
    uint32_t a;
    asm("{ .reg .u64 t; cvta.to.shared.u64 t, %1; cvt.u32.u64 %0, t; }" : "=r"(a) : "l"(p));
    return a;
}
__device__ __forceinline__ uint32_t hi_pair(float a, float b) {
    uint32_t r;
    asm("prmt.b32 %0, %1, %2, 0x7632;" : "=r"(r) : "r"(__float_as_uint(a)), "r"(__float_as_uint(b)));
    return r;
}
__device__ __forceinline__ uint32_t lo_pair(float a, float b) {
    float ra = a - __uint_as_float(__float_as_uint(a) & 0xFFFF0000u);
    float rb = b - __uint_as_float(__float_as_uint(b) & 0xFFFF0000u);
    uint32_t r;
    asm("cvt.rn.bf16x2.f32 %0, %1, %2;" : "=r"(r) : "f"(rb), "f"(ra));
    return r;
}
__device__ __forceinline__ void store_h(__nv_bfloat16* ph, __nv_bfloat16* pl, float h) {
    uint32_t b = __float_as_uint(h);
    *(unsigned short*)ph = (unsigned short)(b >> 16);
    float lo = h - __uint_as_float(b & 0xFFFF0000u);
    *pl = __float2bfloat16(lo);
}

// ---------------- mma.sync / ldmatrix / cp.async primitives ----------------
__device__ __forceinline__ void ldsm4(uint32_t* r, uint32_t a) {
    asm volatile("ldmatrix.sync.aligned.m8n8.x4.shared.b16 {%0,%1,%2,%3}, [%4];"
                 : "=r"(r[0]), "=r"(r[1]), "=r"(r[2]), "=r"(r[3]) : "r"(a));
}
__device__ __forceinline__ void mma_bf16(float* d, const uint32_t* a, const uint32_t* b) {
    asm volatile("mma.sync.aligned.m16n8k16.row.col.f32.bf16.bf16.f32 "
                 "{%0,%1,%2,%3}, {%4,%5,%6,%7}, {%8,%9}, {%0,%1,%2,%3};"
                 : "+f"(d[0]), "+f"(d[1]), "+f"(d[2]), "+f"(d[3])
                 : "r"(a[0]), "r"(a[1]), "r"(a[2]), "r"(a[3]), "r"(b[0]), "r"(b[1]));
}
#define CP16(dst, src) \
    asm volatile("cp.async.cg.shared.global [%0], [%1], 16;" :: "r"(dst), "l"(src))
#define CP_COMMIT() asm volatile("cp.async.commit_group;" ::: "memory")
#define CP_WAIT1()  asm volatile("cp.async.wait_group 1;" ::: "memory")
#define CP_WAIT0()  asm volatile("cp.async.wait_group 0;" ::: "memory")

// ---------------- SMEM tile layout ----------------
// planes: 0=AH 1=AL 2=BH 3=BL ; each 128 rows x 32 bf16, row stride 80B
#define STRIDE   80
#define PLANE    10240
#define SM_TILES 1024
#define SMEM_SZ  (SM_TILES + 8 * PLANE)   // 82944 bytes

__device__ __forceinline__ uint32_t toff(int buf, int p) {
    return SM_TILES + (uint32_t)(buf * 4 + p) * PLANE;
}

// per-warp math on one K=32 chunk: acc += Ah*Bh + Ah*Bl + Al*Bh
__device__ __forceinline__ void mma_tile(float (&acc)[4][4][4], uint32_t smb, int buf,
                                         int wm, int wn, int lane) {
    const uint32_t base = smb + SM_TILES + (uint32_t)buf * 4 * PLANE;
    const uint32_t la = base + (uint32_t)((wm * 64 + (lane & 15)) * STRIDE) + (uint32_t)((lane >> 4) << 4);
    // B: lanes 0-15 -> BH plane, lanes 16-31 -> BL plane (one ldsm4 covers both)
    const uint32_t lb = base + 2 * PLANE + ((lane & 16) ? PLANE : 0)
                        + (uint32_t)((wn * 32 + (lane & 7)) * STRIDE)
                        + (uint32_t)(((lane >> 3) & 1) << 4);
#pragma unroll
    for (int ks = 0; ks < 2; ks++) {
        uint32_t af[4][4], bf[4][4];
#pragma unroll
        for (int mi = 0; mi < 4; mi++) ldsm4(af[mi], la + mi * 16 * STRIDE + ks * 32);
#pragma unroll
        for (int ni = 0; ni < 4; ni++) ldsm4(bf[ni], lb + ni * 8 * STRIDE + ks * 32);
#pragma unroll
        for (int mi = 0; mi < 4; mi++)
#pragma unroll
            for (int ni = 0; ni < 4; ni++) {
                mma_bf16(acc[mi][ni], af[mi], &bf[ni][0]);   // Ah*Bh
                mma_bf16(acc[mi][ni], af[mi], &bf[ni][2]);   // Ah*Bl
            }
#pragma unroll
        for (int mi = 0; mi < 4; mi++) ldsm4(af[mi], la + PLANE + mi * 16 * STRIDE + ks * 32);
#pragma unroll
        for (int mi = 0; mi < 4; mi++)
#pragma unroll
            for (int ni = 0; ni < 4; ni++) mma_bf16(acc[mi][ni], af[mi], &bf[ni][0]);  // Al*Bh
    }
}

// copy 16 bf16 (32B) from each plane pair into smem via cp.async
__device__ __forceinline__ void cp_pair(uint32_t dh, const __nv_bfloat16* sh,
                                        uint32_t dl, const __nv_bfloat16* sl) {
    CP16(dh, sh); CP16(dh + 16, sh + 8);
    CP16(dl, sl); CP16(dl + 16, sl + 8);
}

// ---------------- pre-split kernel: fp32 -> bf16 hi/lo planes ----------------
__global__ __launch_bounds__(256) void split_kernel(const float* __restrict__ s,
                                                    __nv_bfloat16* __restrict__ hq,
                                                    __nv_bfloat16* __restrict__ lq, int n8) {
    int i = blockIdx.x * blockDim.x + threadIdx.x;
    if (i >= n8) return;
    const float4* p = (const float4*)s + (size_t)i * 2;
    float4 v0 = p[0], v1 = p[1];
    uint4 H, L;
    H.x = hi_pair(v0.x, v0.y); H.y = hi_pair(v0.z, v0.w);
    H.z = hi_pair(v1.x, v1.y); H.w = hi_pair(v1.z, v1.w);
    L.x = lo_pair(v0.x, v0.y); L.y = lo_pair(v0.z, v0.w);
    L.z = lo_pair(v1.x, v1.y); L.w = lo_pair(v1.z, v1.w);
    ((uint4*)hq)[i] = H;
    ((uint4*)lq)[i] = L;
}

// ---------------- init ----------------
__global__ void init_kernel() {
    int i = threadIdx.x;
    if (i < NEXP) { g_counts[i] = 0; g_fill[i] = 0; }
}

// ---------------- routing ----------------
__global__ __launch_bounds__(256) void route_kernel(const float* __restrict__ x,
                                                    const float* __restrict__ gw,
                                                    const float* __restrict__ eb) {
    const int t = blockIdx.x;
    __shared__ float xs[HDIM];
    __shared__ float sc[NEXP];
    __shared__ float sfc[NEXP];
    const int tid = threadIdx.x;
    const float* xr = x + (size_t)t * HDIM;
    #pragma unroll
    for (int i = 0; i < HDIM / 256; i++) xs[tid + i * 256] = xr[tid + i * 256];
    __syncthreads();

    const int warp = tid >> 5, lane = tid & 31;
    for (int q = 0; q < NEXP / 8; q++) {
        const int e = warp * 8 + q;
        const float* gwe = gw + (size_t)e * HDIM;
        float s = 0.f;
        #pragma unroll
        for (int i = 0; i < HDIM / 32; i++)
            s = fmaf(xs[i * 32 + lane], gwe[i * 32 + lane], s);
        #pragma unroll
        for (int off = 16; off; off >>= 1) s += __shfl_down_sync(0xffffffffu, s, off);
        if (lane == 0) {
            float sig = 1.f / (1.f + expf(-s));
            sc[e] = sig;
            sfc[e] = sig + eb[e];
        }
    }
    __syncthreads();

    if (tid == 0) {
        float gsc[NGRP];
        #pragma unroll
        for (int g = 0; g < NGRP; g++) {
            float m1 = -1e30f, m2 = -1e30f;
            #pragma unroll
            for (int j = 0; j < NEXP / NGRP; j++) {
                float v = sfc[g * (NEXP / NGRP) + j];
                if (v > m1) { m2 = m1; m1 = v; } else if (v > m2) { m2 = v; }
            }
            gsc[g] = m1 + m2;
        }
        bool gsel[NGRP];
        #pragma unroll
        for (int g = 0; g < NGRP; g++) gsel[g] = false;
        for (int it = 0; it < TGRP; it++) {
            float best = -1e30f; int bi = 0;
            #pragma unroll
            for (int g = 0; g < NGRP; g++)
                if (!gsel[g] && gsc[g] > best) { best = gsc[g]; bi = g; }
            gsel[bi] = true;
        }
        float tmp[NEXP];
        #pragma unroll
        for (int e = 0; e < NEXP; e++)
            tmp[e] = gsel[e / (NEXP / NGRP)] ? sfc[e] : 0.0f;
        int   idx[TOPK];
        float wv[TOPK];
        float wsum = 0.f;
        for (int k = 0; k < TOPK; k++) {
            float best = -1e30f; int bi = 0;
            #pragma unroll
            for (int e = 0; e < NEXP; e++)
                if (tmp[e] > best) { best = tmp[e]; bi = e; }
            idx[k] = bi; tmp[bi] = -1e30f;
            wv[k] = sc[bi]; wsum += wv[k];
        }
        float inv = SCALE / (wsum + 1e-20f);
        for (int k = 0; k < TOPK; k++) {
            g_topk_idx[t * TOPK + k] = idx[k];
            g_topk_w[t * TOPK + k] = wv[k] * inv;
            atomicAdd(&g_counts[idx[k]], 1);
        }
    }
}

__global__ void scan_kernel() {
    if (threadIdx.x == 0) {
        int run = 0;
        for (int e = 0; e < NEXP; e++) {
            int c = g_counts[e];
            int cc = c < CAPE ? c : CAPE;
            g_offsets[e] = run;
            g_ecount[e] = cc;
            run += cc;
        }
    }
}

__global__ void assign_kernel() {
    int s = blockIdx.x * blockDim.x + threadIdx.x;
    if (s >= SKTOT) return;
    int e = g_topk_idx[s];
    int p = atomicAdd(&g_fill[e], 1);
    if (p < CAPE) {
        int r = g_offsets[e] + p;
        g_row_token[r] = s / TOPK;
        g_row_weight[r] = g_topk_w[s];
    }
}

// =====================================================================
// Expert GEMM1: gathered x-planes @ interleaved(w1,w3)-planes -> SwiGLU
// =====================================================================
__global__ void __launch_bounds__(256, 2) eg1_kernel() {
    extern __shared__ char sm[];
    const int tid = threadIdx.x, lane = tid & 31, wid = tid >> 5;
    const int wm = wid & 1, wn = wid >> 1;
    const int e  = blockIdx.z;
    const int me = g_ecount[e];
    const int m0 = blockIdx.y * 128;
    if (m0 >= me) return;
    const int f0 = blockIdx.x * 64;
    const int roff = g_offsets[e];
    const uint32_t smb = smem_u32(sm);

    int* toks = (int*)sm;
    if (tid < 128) {
        int m = m0 + tid;
        toks[tid] = g_row_token[roff + ((m < me) ? m : 0)];
    }
    __syncthreads();

    const int lr = tid >> 1, kseg = (tid & 1) * 16;
    const uint32_t soff = (uint32_t)(lr * STRIDE + kseg * 2);
    const __nv_bfloat16* axh = g_xh + (size_t)toks[lr] * HDIM + kseg;
    const __nv_bfloat16* axl = g_xl + (size_t)toks[lr] * HDIM + kseg;
    const size_t bofs = ((size_t)e * FDIM + f0 + (lr >> 1)) * HDIM + kseg;
    const __nv_bfloat16* bxh = ((lr & 1) ? g_w3h : g_w1h) + bofs;
    const __nv_bfloat16* bxl = ((lr & 1) ? g_w3l : g_w1l) + bofs;

    float acc[4][4][4];
#pragma unroll
    for (int i = 0; i < 4; i++)
#pragma unroll
        for (int j = 0; j < 4; j++)
#pragma unroll
            for (int k = 0; k < 4; k++) acc[i][j][k] = 0.f;

    cp_pair(smb + toff(0, 0) + soff, axh, smb + toff(0, 1) + soff, axl);
    cp_pair(smb + toff(0, 2) + soff, bxh, smb + toff(0, 3) + soff, bxl);
    CP_COMMIT();

    int buf = 0;
    const int NCH = HDIM / 32;
    for (int ch = 0; ch < NCH; ch++) {
        if (ch + 1 < NCH) {
            int k0 = (ch + 1) * 32;
            cp_pair(smb + toff(buf ^ 1, 0) + soff, axh + k0, smb + toff(buf ^ 1, 1) + soff, axl + k0);
            cp_pair(smb + toff(buf ^ 1, 2) + soff, bxh + k0, smb + toff(buf ^ 1, 3) + soff, bxl + k0);
            CP_COMMIT(); CP_WAIT1();
        } else CP_WAIT0();
        __syncthreads();
        mma_tile(acc, smb, buf, wm, wn, lane);
        __syncthreads();
        buf ^= 1;
    }

#pragma unroll
    for (int mi = 0; mi < 4; mi++) {
        int r = m0 + wm * 64 + mi * 16 + (lane >> 2);
#pragma unroll
        for (int ni = 0; ni < 4; ni++) {
            int lc = f0 + wn * 16 + ni * 4 + (lane & 3);
            float* d = acc[mi][ni];
            if (r < me) {
                float h = silu_mul(d[0], d[1]);
                size_t o = (size_t)(roff + r) * FDIM + lc;
                store_h(g_hbuf_hi + o, g_hbuf_lo + o, h);
            }
            if (r + 8 < me) {
                float h = silu_mul(d[2], d[3]);
                size_t o = (size_t)(roff + r + 8) * FDIM + lc;
                store_h(g_hbuf_hi + o, g_hbuf_lo + o, h);
            }
        }
    }
}

// =====================================================================
// Expert GEMM2: hbuf planes @ w2 planes -> weighted atomicAdd into out
// =====================================================================
__global__ void __launch_bounds__(256, 2) eg2_kernel(float* __restrict__ out) {
    extern __shared__ char sm[];
    const int tid = threadIdx.x, lane = tid & 31, wid = tid >> 5;
    const int wm = wid & 1, wn = wid >> 1;
    const int e  = blockIdx.z;
    const int me = g_ecount[e];
    const int m0 = blockIdx.y * 128;
    if (m0 >= me) return;
    const int n0 = blockIdx.x * 128;
    const int roff = g_offsets[e];
    const uint32_t smb = smem_u32(sm);

    int*   toks = (int*)sm;
    float* wro  = (float*)(sm + 512);
    if (tid < 128) {
        int m = m0 + tid;
        bool v = m < me;
        toks[tid] = v ? g_row_token[roff + m] : 0;
        wro[tid]  = v ? g_row_weight[roff + m] : 0.f;
    }
    __syncthreads();

    const int lr = tid >> 1, kseg = (tid & 1) * 16;
    const uint32_t soff = (uint32_t)(lr * STRIDE + kseg * 2);
    int mm = m0 + lr;
    size_t arow = (size_t)(roff + ((mm < me) ? mm : (me - 1)));
    const __nv_bfloat16* axh = g_hbuf_hi + arow * FDIM + kseg;
    const __nv_bfloat16* axl = g_hbuf_lo + arow * FDIM + kseg;
    const size_t bofs = ((size_t)e * HDIM + n0 + lr) * FDIM + kseg;
    const __nv_bfloat16* bxh = g_w2h + bofs;
    const __nv_bfloat16* bxl = g_w2l + bofs;

    float acc[4][4][4];
#pragma unroll
    for (int i = 0; i < 4; i++)
#pragma unroll
        for (int j = 0; j < 4; j++)
#pragma unroll
            for (int k = 0; k < 4; k++) acc[i][j][k] = 0.f;

    cp_pair(smb + toff(0, 0) + soff, axh, smb + toff(0, 1) + soff, axl);
    cp_pair(smb + toff(0, 2) + soff, bxh, smb + toff(0, 3) + soff, bxl);
    CP_COMMIT();

    int buf = 0;
    const int NCH = FDIM / 32;
    for (int ch = 0; ch < NCH; ch++) {
        if (ch + 1 < NCH) {
            int k0 = (ch + 1) * 32;
            cp_pair(smb + toff(buf ^ 1, 0) + soff, axh + k0, smb + toff(buf ^ 1, 1) + soff, axl + k0);
            cp_pair(smb + toff(buf ^ 1, 2) + soff, bxh + k0, smb + toff(buf ^ 1, 3) + soff, bxl + k0);
            CP_COMMIT(); CP_WAIT1();
        } else CP_WAIT0();
        __syncthreads();
        mma_tile(acc, smb, buf, wm, wn, lane);
        __syncthreads();
        buf ^= 1;
    }

#pragma unroll
    for (int mi = 0; mi < 4; mi++) {
        int lrow = wm * 64 + mi * 16 + (lane >> 2);
        int r = m0 + lrow;
        int t0 = toks[lrow], t1 = toks[lrow + 8];
        float w0 = wro[lrow], w1v = wro[lrow + 8];
#pragma unroll
        for (int ni = 0; ni < 4; ni++) {
            int col = n0 + wn * 32 + ni * 8 + 2 * (lane & 3);
            float* d = acc[mi][ni];
            if (r < me) {
                atomicAdd(out + (size_t)t0 * HDIM + col,     d[0] * w0);
                atomicAdd(out + (size_t)t0 * HDIM + col + 1, d[1] * w0);
            }
            if (r + 8 < me) {
                atomicAdd(out + (size_t)t1 * HDIM + col,     d[2] * w1v);
                atomicAdd(out + (size_t)t1 * HDIM + col + 1, d[3] * w1v);
            }
        }
    }
}

// =====================================================================
// Shared GEMM1: x planes @ interleaved(sg,su) planes -> SwiGLU -> hs
// =====================================================================
__global__ void __launch_bounds__(256, 2) sg1_kernel() {
    extern __shared__ char sm[];
    const int tid = threadIdx.x, lane = tid & 31, wid = tid >> 5;
    const int wm = wid & 1, wn = wid >> 1;
    const int m0 = blockIdx.y * 128;
    const int f0 = blockIdx.x * 64;
    const uint32_t smb = smem_u32(sm);

    const int lr = tid >> 1, kseg = (tid & 1) * 16;
    const uint32_t soff = (uint32_t)(lr * STRIDE + kseg * 2);
    const __nv_bfloat16* axh = g_xh + (size_t)(m0 + lr) * HDIM + kseg;
    const __nv_bfloat16* axl = g_xl + (size_t)(m0 + lr) * HDIM + kseg;
    const size_t bofs = (size_t)(f0 + (lr >> 1)) * HDIM + kseg;
    const __nv_bfloat16* bxh = ((lr & 1) ? g_suh : g_sgh) + bofs;
    const __nv_bfloat16* bxl = ((lr & 1) ? g_sul : g_sgl) + bofs;

    float acc[4][4][4];
#pragma unroll
    for (int i = 0; i < 4; i++)
#pragma unroll
        for (int j = 0; j < 4; j++)
#pragma unroll
            for (int k = 0; k < 4; k++) acc[i][j][k] = 0.f;

    cp_pair(smb + toff(0, 0) + soff, axh, smb + toff(0, 1) + soff, axl);
    cp_pair(smb + toff(0, 2) + soff, bxh, smb + toff(0, 3) + soff, bxl);
    CP_COMMIT();

    int buf = 0;
    const int NCH = HDIM / 32;
    for (int ch = 0; ch < NCH; ch++) {
        if (ch + 1 < NCH) {
            int k0 = (ch + 1) * 32;
            cp_pair(smb + toff(buf ^ 1, 0) + soff, axh + k0, smb + toff(buf ^ 1, 1) + soff, axl + k0);
            cp_pair(smb + toff(buf ^ 1, 2) + soff, bxh + k0, smb + toff(buf ^ 1, 3) + soff, bxl + k0);
            CP_COMMIT(); CP_WAIT1();
        } else CP_WAIT0();
        __syncthreads();
        mma_tile(acc, smb, buf, wm, wn, lane);
        __syncthreads();
        buf ^= 1;
    }

#pragma unroll
    for (int mi = 0; mi < 4; mi++) {
        int r = m0 + wm * 64 + mi * 16 + (lane >> 2);
#pragma unroll
        for (int ni = 0; ni < 4; ni++) {
            int lc = f0 + wn * 16 + ni * 4 + (lane & 3);
            float* d = acc[mi][ni];
            float h0 = silu_mul(d[0], d[1]);
            float h1 = silu_mul(d[2], d[3]);
            size_t o0 = (size_t)r * F2DIM + lc;
            size_t o1 = (size_t)(r + 8) * F2DIM + lc;
            store_h(g_hs_hi + o0, g_hs_lo + o0, h0);
            store_h(g_hs_hi + o1, g_hs_lo + o1, h1);
        }
    }
}

// =====================================================================
// Shared GEMM2: hs planes @ sd planes -> overwrite out
// =====================================================================
__global__ void __launch_bounds__(256, 2) sg2_kernel(float* __restrict__ out) {
    extern __shared__ char sm[];
    const int tid = threadIdx.x, lane = tid & 31, wid = tid >> 5;
    const int wm = wid & 1, wn = wid >> 1;
    const int m0 = blockIdx.y * 128;
    const int n0 = blockIdx.x * 128;
    const uint32_t smb = smem_u32(sm);

    const int lr = tid >> 1, kseg = (tid & 1) * 16;
    const uint32_t soff = (uint32_t)(lr * STRIDE + kseg * 2);
    const __nv_bfloat16* axh = g_hs_hi + (size_t)(m0 + lr) * F2DIM + kseg;
    const __nv_bfloat16* axl = g_hs_lo + (size_t)(m0 + lr) * F2DIM + kseg;
    const size_t bofs = (size_t)(n0 + lr) * F2DIM + kseg;
    const __nv_bfloat16* bxh = g_sdh + bofs;
    const __nv_bfloat16* bxl = g_sdl + bofs;

    float acc[4][4][4];
#pragma unroll
    for (int i = 0; i < 4; i++)
#pragma unroll
        for (int j = 0; j < 4; j++)
#pragma unroll
            for (int k = 0; k < 4; k++) acc[i][j][k] = 0.f;

    cp_pair(smb + toff(0, 0) + soff, axh, smb + toff(0, 1) + soff, axl);
    cp_pair(smb + toff(0, 2) + soff, bxh, smb + toff(0, 3) + soff, bxl);
    CP_COMMIT();

    int buf = 0;
    const int NCH = F2DIM / 32;
    for (int ch = 0; ch < NCH; ch++) {
        if (ch + 1 < NCH) {
            int k0 = (ch + 1) * 32;
            cp_pair(smb + toff(buf ^ 1, 0) + soff, axh + k0, smb + toff(buf ^ 1, 1) + soff, axl + k0);
            cp_pair(smb + toff(buf ^ 1, 2) + soff, bxh + k0, smb + toff(buf ^ 1, 3) + soff, bxl + k0);
            CP_COMMIT(); CP_WAIT1();
        } else CP_WAIT0();
        __syncthreads();
        mma_tile(acc, smb, buf, wm, wn, lane);
        __syncthreads();
        buf ^= 1;
    }

#pragma unroll
    for (int mi = 0; mi < 4; mi++) {
        int r = m0 + wm * 64 + mi * 16 + (lane >> 2);
#pragma unroll
        for (int ni = 0; ni < 4; ni++) {
            int col = n0 + wn * 32 + ni * 8 + 2 * (lane & 3);
            float* d = acc[mi][ni];
            *(float2*)(out + (size_t)r * HDIM + col)       = make_float2(d[0], d[1]);
            *(float2*)(out + (size_t)(r + 8) * HDIM + col) = make_float2(d[2], d[3]);
        }
    }
}

// ---------------- launch ----------------
extern "C" void kernel_launch(void* const* d_in, const int* in_sizes, int n_in,
                              void* d_out, int out_size) {
    const float* x   = (const float*)d_in[0];
    const float* gw  = (const float*)d_in[1];
    const float* eb  = (const float*)d_in[2];
    const float* w1  = (const float*)d_in[3];
    const float* w2  = (const float*)d_in[4];
    const float* w3  = (const float*)d_in[5];
    const float* sg  = (const float*)d_in[6];
    const float* su  = (const float*)d_in[7];
    const float* sd  = (const float*)d_in[8];
    float* out = (float*)d_out;

    static bool init_done = false;
    static __nv_bfloat16 *pw1h, *pw1l, *pw3h, *pw3l, *pw2h, *pw2l;
    static __nv_bfloat16 *psgh, *psgl, *psuh, *psul, *psdh, *psdl, *pxh, *pxl;
    if (!init_done) {
        cudaFuncSetAttribute(eg1_kernel, cudaFuncAttributeMaxDynamicSharedMemorySize, SMEM_SZ);
        cudaFuncSetAttribute(eg2_kernel, cudaFuncAttributeMaxDynamicSharedMemorySize, SMEM_SZ);
        cudaFuncSetAttribute(sg1_kernel, cudaFuncAttributeMaxDynamicSharedMemorySize, SMEM_SZ);
        cudaFuncSetAttribute(sg2_kernel, cudaFuncAttributeMaxDynamicSharedMemorySize, SMEM_SZ);
        cudaGetSymbolAddress((void**)&pw1h, g_w1h); cudaGetSymbolAddress((void**)&pw1l, g_w1l);
        cudaGetSymbolAddress((void**)&pw3h, g_w3h); cudaGetSymbolAddress((void**)&pw3l, g_w3l);
        cudaGetSymbolAddress((void**)&pw2h, g_w2h); cudaGetSymbolAddress((void**)&pw2l, g_w2l);
        cudaGetSymbolAddress((void**)&psgh, g_sgh); cudaGetSymbolAddress((void**)&psgl, g_sgl);
        cudaGetSymbolAddress((void**)&psuh, g_suh); cudaGetSymbolAddress((void**)&psul, g_sul);
        cudaGetSymbolAddress((void**)&psdh, g_sdh); cudaGetSymbolAddress((void**)&psdl, g_sdl);
        cudaGetSymbolAddress((void**)&pxh,  g_xh);  cudaGetSymbolAddress((void**)&pxl,  g_xl);
        init_done = true;
    }

    // pre-split everything to bf16 hi/lo planes
    const int nW = NEXP * FDIM * HDIM / 8;      // 4.19M
    const int nS = F2DIM * HDIM / 8;            // 131072
    const int nX = TOK * HDIM / 8;              // 262144
    split_kernel<<<nW / 256, 256>>>(w1, pw1h, pw1l, nW);
    split_kernel<<<nW / 256, 256>>>(w3, pw3h, pw3l, nW);
    split_kernel<<<nW / 256, 256>>>(w2, pw2h, pw2l, nW);
    split_kernel<<<nS / 256, 256>>>(sg, psgh, psgl, nS);
    split_kernel<<<nS / 256, 256>>>(su, psuh, psul, nS);
    split_kernel<<<nS / 256, 256>>>(sd, psdh, psdl, nS);
    split_kernel<<<nX / 256, 256>>>(x,  pxh,  pxl,  nX);

    init_kernel<<<1, 64>>>();
    route_kernel<<<TOK, 256>>>(x, gw, eb);
    scan_kernel<<<1, 32>>>();
    assign_kernel<<<SKTOT / 256, 256>>>();

    // expert up-proj + SwiGLU -> hbuf planes
    eg1_kernel<<<dim3(FDIM / 64, CAPE / 128, NEXP), 256, SMEM_SZ>>>();

    // shared expert: sg1 -> hs planes, sg2 overwrites out
    sg1_kernel<<<dim3(F2DIM / 64, TOK / 128), 256, SMEM_SZ>>>();
    sg2_kernel<<<dim3(HDIM / 128, TOK / 128), 256, SMEM_SZ>>>(out);

    // expert down-proj + weighted scatter-add
    eg2_kernel<<<dim3(HDIM / 128, CAPE / 128, NEXP), 256, SMEM_SZ>>>(out);
}

// round 7
// speedup vs baseline: 1.4698x; 1.4698x over previous
#include <cuda_runtime.h>
#include <cuda_fp16.h>
#include <math.h>
#include <stdint.h>

// ---------------- problem constants ----------------
#define TOK     2048
#define HDIM    1024
#define FDIM    512
#define F2DIM   1024
#define NEXP    64
#define TOPK    8
#define NGRP    8
#define TGRP    4
#define CAPE    1024
#define SKTOT   (TOK*TOPK)
#define SCALE   2.5f

// ---------------- device scratch: fp16 planes ----------------
__device__ __half g_x_h[TOK * HDIM];
__device__ __half g_x_l[TOK * HDIM];
__device__ __half g_sg_h[F2DIM * HDIM];
__device__ __half g_su_h[F2DIM * HDIM];
__device__ __half g_sd_h[HDIM * F2DIM];
__device__ __half g_hb_h[SKTOT * FDIM];
__device__ __half g_hb_l[SKTOT * FDIM];
__device__ __half g_hs_h[TOK * F2DIM];
__device__ __half g_hs_l[TOK * F2DIM];
__device__ int   g_topk_idx[SKTOT];
__device__ float g_topk_w[SKTOT];
__device__ int   g_counts[NEXP];
__device__ int   g_fill[NEXP];
__device__ int   g_offsets[NEXP];
__device__ int   g_ecount[NEXP];
__device__ int   g_row_token[SKTOT];
__device__ float g_row_weight[SKTOT];

// ---------------- helpers ----------------
__device__ __forceinline__ float silu_mul(float g, float u) {
    return g / (1.f + expf(-g)) * u;
}
__device__ __forceinline__ uint32_t smem_u32(const void* p) {
    uint32_t a;
    asm("{ .reg .u64 t; cvta.to.shared.u64 t, %1; cvt.u32.u64 %0, t; }" : "=r"(a) : "l"(p));
    return a;
}
// pack rn-fp16 of (a,b): low half = a
__device__ __forceinline__ uint32_t h_pair(float a, float b) {
    uint32_t r;
    asm("cvt.rn.f16x2.f32 %0, %1, %2;" : "=r"(r) : "f"(b), "f"(a));
    return r;
}
__device__ __forceinline__ void store_h2(__half* ph, __half* pl, float h) {
    __half hh = __float2half_rn(h);
    *ph = hh;
    *pl = __float2half_rn(h - __half2float(hh));
}

// ---------------- mma.sync / ldmatrix / cp.async primitives ----------------
__device__ __forceinline__ void ldsm4(uint32_t* r, uint32_t a) {
    asm volatile("ldmatrix.sync.aligned.m8n8.x4.shared.b16 {%0,%1,%2,%3}, [%4];"
                 : "=r"(r[0]), "=r"(r[1]), "=r"(r[2]), "=r"(r[3]) : "r"(a));
}
__device__ __forceinline__ void mma_f16(float* d, const uint32_t* a, const uint32_t* b) {
    asm volatile("mma.sync.aligned.m16n8k16.row.col.f32.f16.f16.f32 "
                 "{%0,%1,%2,%3}, {%4,%5,%6,%7}, {%8,%9}, {%0,%1,%2,%3};"
                 : "+f"(d[0]), "+f"(d[1]), "+f"(d[2]), "+f"(d[3])
                 : "r"(a[0]), "r"(a[1]), "r"(a[2]), "r"(a[3]), "r"(b[0]), "r"(b[1]));
}
#define CP16(dst, src) \
    asm volatile("cp.async.cg.shared.global [%0], [%1], 16;" :: "r"(dst), "l"(src))
#define CP_COMMIT() asm volatile("cp.async.commit_group;" ::: "memory")
#define CP_WAIT1()  asm volatile("cp.async.wait_group 1;" ::: "memory")
#define CP_WAIT0()  asm volatile("cp.async.wait_group 0;" ::: "memory")

// ---------------- SMEM tile layout ----------------
// planes: 0=A_hi 1=A_lo 2=B ; each 128 rows x 32 fp16, row stride 80B
#define STRIDE   80
#define PLANE    10240
#define SM_TILES 1024
#define SMEM_SZ  (SM_TILES + 6 * PLANE)   // 62464 bytes -> 2 CTAs/SM

__device__ __forceinline__ uint32_t toff(int buf, int p) {
    return SM_TILES + (uint32_t)(buf * 3 + p) * PLANE;
}

// per-warp math on one K=32 chunk: acc += Ah*B + Al*B
__device__ __forceinline__ void mma_tile(float (&acc)[4][4][4], uint32_t smb, int buf,
                                         int wm, int wn, int lane) {
    const uint32_t base = smb + SM_TILES + (uint32_t)buf * 3 * PLANE;
    const uint32_t la = base + (uint32_t)((wm * 64 + (lane & 15)) * STRIDE) + (uint32_t)((lane >> 4) << 4);
    // B: one ldsm4 covers two n8 fragments (lanes 16-31 -> +8 rows)
    const uint32_t lb = base + 2 * PLANE + ((lane & 16) ? 8 * STRIDE : 0)
                        + (uint32_t)((wn * 32 + (lane & 7)) * STRIDE)
                        + (uint32_t)(((lane >> 3) & 1) << 4);
#pragma unroll
    for (int ks = 0; ks < 2; ks++) {
        const int ko = ks * 32;
        uint32_t ah[4][4], al_[4][4], bf[2][4];
#pragma unroll
        for (int mi = 0; mi < 4; mi++) ldsm4(ah[mi], la + mi * 16 * STRIDE + ko);
#pragma unroll
        for (int mi = 0; mi < 4; mi++) ldsm4(al_[mi], la + PLANE + mi * 16 * STRIDE + ko);
        ldsm4(bf[0], lb + ko);
        ldsm4(bf[1], lb + 16 * STRIDE + ko);
#pragma unroll
        for (int mi = 0; mi < 4; mi++)
#pragma unroll
            for (int ni = 0; ni < 4; ni++) {
                const uint32_t* b = &bf[ni >> 1][(ni & 1) * 2];
                mma_f16(acc[mi][ni], ah[mi], b);
                mma_f16(acc[mi][ni], al_[mi], b);
            }
    }
}

// ---------------- loaders ----------------
__device__ __forceinline__ void ldg16f(float* r, const float* __restrict__ p) {
#pragma unroll
    for (int i = 0; i < 4; i++) *(float4*)(r + i * 4) = *(const float4*)(p + i * 4);
}
// convert 16 fp32 -> 16 rn-fp16, store 32B
__device__ __forceinline__ void sts_h16(char* p, const float* v) {
    uint4 H0, H1;
    H0.x = h_pair(v[0], v[1]);   H0.y = h_pair(v[2], v[3]);
    H0.z = h_pair(v[4], v[5]);   H0.w = h_pair(v[6], v[7]);
    H1.x = h_pair(v[8], v[9]);   H1.y = h_pair(v[10], v[11]);
    H1.z = h_pair(v[12], v[13]); H1.w = h_pair(v[14], v[15]);
    *(uint4*)p = H0; *(uint4*)(p + 16) = H1;
}
// cp 16 fp16 (32B) from hi+lo planes
__device__ __forceinline__ void cpA(uint32_t dh, const __half* sh, uint32_t dl, const __half* sl) {
    CP16(dh, sh); CP16(dh + 16, sh + 8);
    CP16(dl, sl); CP16(dl + 16, sl + 8);
}

// ---------------- presplit kernels ----------------
__global__ __launch_bounds__(256) void split2_kernel(const float* __restrict__ s,
                                                     __half* __restrict__ hq,
                                                     __half* __restrict__ lq) {
    int i = blockIdx.x * blockDim.x + threadIdx.x;
    const float4* p = (const float4*)s + (size_t)i * 2;
    float4 v0 = p[0], v1 = p[1];
    float vv[8] = {v0.x, v0.y, v0.z, v0.w, v1.x, v1.y, v1.z, v1.w};
    uint4 H, L;
    uint32_t* hp = (uint32_t*)&H;
    uint32_t* lp = (uint32_t*)&L;
#pragma unroll
    for (int j = 0; j < 4; j++) {
        __half2 h = __floats2half2_rn(vv[2 * j], vv[2 * j + 1]);
        float2 bk = __half22float2(h);
        __half2 l = __floats2half2_rn(vv[2 * j] - bk.x, vv[2 * j + 1] - bk.y);
        hp[j] = *(uint32_t*)&h;
        lp[j] = *(uint32_t*)&l;
    }
    ((uint4*)hq)[i] = H;
    ((uint4*)lq)[i] = L;
}
__global__ __launch_bounds__(256) void split1_kernel(const float* __restrict__ s,
                                                     __half* __restrict__ hq) {
    int i = blockIdx.x * blockDim.x + threadIdx.x;
    const float4* p = (const float4*)s + (size_t)i * 2;
    float4 v0 = p[0], v1 = p[1];
    uint4 H;
    H.x = h_pair(v0.x, v0.y); H.y = h_pair(v0.z, v0.w);
    H.z = h_pair(v1.x, v1.y); H.w = h_pair(v1.z, v1.w);
    ((uint4*)hq)[i] = H;
}

// ---------------- init ----------------
__global__ void init_kernel() {
    int i = threadIdx.x;
    if (i < NEXP) { g_counts[i] = 0; g_fill[i] = 0; }
}

// ---------------- routing ----------------
__global__ __launch_bounds__(256) void route_kernel(const float* __restrict__ x,
                                                    const float* __restrict__ gw,
                                                    const float* __restrict__ eb) {
    const int t = blockIdx.x;
    __shared__ float xs[HDIM];
    __shared__ float sc[NEXP];
    __shared__ float sfc[NEXP];
    const int tid = threadIdx.x;
    const float* xr = x + (size_t)t * HDIM;
    #pragma unroll
    for (int i = 0; i < HDIM / 256; i++) xs[tid + i * 256] = xr[tid + i * 256];
    __syncthreads();

    const int warp = tid >> 5, lane = tid & 31;
    for (int q = 0; q < NEXP / 8; q++) {
        const int e = warp * 8 + q;
        const float* gwe = gw + (size_t)e * HDIM;
        float s = 0.f;
        #pragma unroll
        for (int i = 0; i < HDIM / 32; i++)
            s = fmaf(xs[i * 32 + lane], gwe[i * 32 + lane], s);
        #pragma unroll
        for (int off = 16; off; off >>= 1) s += __shfl_down_sync(0xffffffffu, s, off);
        if (lane == 0) {
            float sig = 1.f / (1.f + expf(-s));
            sc[e] = sig;
            sfc[e] = sig + eb[e];
        }
    }
    __syncthreads();

    if (tid == 0) {
        float gsc[NGRP];
        #pragma unroll
        for (int g = 0; g < NGRP; g++) {
            float m1 = -1e30f, m2 = -1e30f;
            #pragma unroll
            for (int j = 0; j < NEXP / NGRP; j++) {
                float v = sfc[g * (NEXP / NGRP) + j];
                if (v > m1) { m2 = m1; m1 = v; } else if (v > m2) { m2 = v; }
            }
            gsc[g] = m1 + m2;
        }
        bool gsel[NGRP];
        #pragma unroll
        for (int g = 0; g < NGRP; g++) gsel[g] = false;
        for (int it = 0; it < TGRP; it++) {
            float best = -1e30f; int bi = 0;
            #pragma unroll
            for (int g = 0; g < NGRP; g++)
                if (!gsel[g] && gsc[g] > best) { best = gsc[g]; bi = g; }
            gsel[bi] = true;
        }
        float tmp[NEXP];
        #pragma unroll
        for (int e = 0; e < NEXP; e++)
            tmp[e] = gsel[e / (NEXP / NGRP)] ? sfc[e] : 0.0f;
        int   idx[TOPK];
        float wv[TOPK];
        float wsum = 0.f;
        for (int k = 0; k < TOPK; k++) {
            float best = -1e30f; int bi = 0;
            #pragma unroll
            for (int e = 0; e < NEXP; e++)
                if (tmp[e] > best) { best = tmp[e]; bi = e; }
            idx[k] = bi; tmp[bi] = -1e30f;
            wv[k] = sc[bi]; wsum += wv[k];
        }
        float inv = SCALE / (wsum + 1e-20f);
        for (int k = 0; k < TOPK; k++) {
            g_topk_idx[t * TOPK + k] = idx[k];
            g_topk_w[t * TOPK + k] = wv[k] * inv;
            atomicAdd(&g_counts[idx[k]], 1);
        }
    }
}

__global__ void scan_kernel() {
    if (threadIdx.x == 0) {
        int run = 0;
        for (int e = 0; e < NEXP; e++) {
            int c = g_counts[e];
            int cc = c < CAPE ? c : CAPE;
            g_offsets[e] = run;
            g_ecount[e] = cc;
            run += cc;
        }
    }
}

__global__ void assign_kernel() {
    int s = blockIdx.x * blockDim.x + threadIdx.x;
    if (s >= SKTOT) return;
    int e = g_topk_idx[s];
    int p = atomicAdd(&g_fill[e], 1);
    if (p < CAPE) {
        int r = g_offsets[e] + p;
        g_row_token[r] = s / TOPK;
        g_row_weight[r] = g_topk_w[s];
    }
}

// =====================================================================
// Expert GEMM1: x planes (2) @ interleaved(w1,w3) 1-plane -> SwiGLU -> hbuf planes
// =====================================================================
__global__ void __launch_bounds__(256, 2) eg1_kernel(const float* __restrict__ w1,
                                                     const float* __restrict__ w3) {
    extern __shared__ char sm[];
    const int tid = threadIdx.x, lane = tid & 31, wid = tid >> 5;
    const int wm = wid & 1, wn = wid >> 1;
    const int e  = blockIdx.z;
    const int me = g_ecount[e];
    const int m0 = blockIdx.y * 128;
    if (m0 >= me) return;
    const int f0 = blockIdx.x * 64;
    const int roff = g_offsets[e];
    const uint32_t smb = smem_u32(sm);

    int* toks = (int*)sm;
    if (tid < 128) {
        int m = m0 + tid;
        toks[tid] = g_row_token[roff + ((m < me) ? m : 0)];
    }
    __syncthreads();

    const int lr = tid >> 1, kseg = (tid & 1) * 16;
    const uint32_t soff = (uint32_t)(lr * STRIDE + kseg * 2);
    const __half* axh = g_x_h + (size_t)toks[lr] * HDIM + kseg;
    const __half* axl = g_x_l + (size_t)toks[lr] * HDIM + kseg;
    const float* bp = ((lr & 1) ? w3 : w1) + ((size_t)e * FDIM + f0 + (lr >> 1)) * HDIM + kseg;

    float acc[4][4][4];
#pragma unroll
    for (int i = 0; i < 4; i++)
#pragma unroll
        for (int j = 0; j < 4; j++)
#pragma unroll
            for (int k = 0; k < 4; k++) acc[i][j][k] = 0.f;

    // prologue
    cpA(smb + toff(0, 0) + soff, axh, smb + toff(0, 1) + soff, axl);
    {
        float rb[16];
        ldg16f(rb, bp);
        sts_h16(sm + toff(0, 2) + soff, rb);
    }
    CP_COMMIT();
    float rbn[16];
    ldg16f(rbn, bp + 32);

    int buf = 0;
    const int NCH = HDIM / 32;
    for (int ch = 0; ch < NCH; ch++) {
        if (ch + 1 < NCH) {
            int k0 = (ch + 1) * 32;
            cpA(smb + toff(buf ^ 1, 0) + soff, axh + k0, smb + toff(buf ^ 1, 1) + soff, axl + k0);
            sts_h16(sm + toff(buf ^ 1, 2) + soff, rbn);
            CP_COMMIT(); CP_WAIT1();
            if (ch + 2 < NCH) ldg16f(rbn, bp + (ch + 2) * 32);
        } else CP_WAIT0();
        __syncthreads();
        mma_tile(acc, smb, buf, wm, wn, lane);
        __syncthreads();
        buf ^= 1;
    }

#pragma unroll
    for (int mi = 0; mi < 4; mi++) {
        int r = m0 + wm * 64 + mi * 16 + (lane >> 2);
#pragma unroll
        for (int ni = 0; ni < 4; ni++) {
            int lc = f0 + wn * 16 + ni * 4 + (lane & 3);
            float* d = acc[mi][ni];
            if (r < me) {
                size_t o = (size_t)(roff + r) * FDIM + lc;
                store_h2(g_hb_h + o, g_hb_l + o, silu_mul(d[0], d[1]));
            }
            if (r + 8 < me) {
                size_t o = (size_t)(roff + r + 8) * FDIM + lc;
                store_h2(g_hb_h + o, g_hb_l + o, silu_mul(d[2], d[3]));
            }
        }
    }
}

// =====================================================================
// Expert GEMM2: hbuf planes @ w2 1-plane -> weighted atomicAdd into out
// =====================================================================
__global__ void __launch_bounds__(256, 2) eg2_kernel(const float* __restrict__ w2,
                                                     float* __restrict__ out) {
    extern __shared__ char sm[];
    const int tid = threadIdx.x, lane = tid & 31, wid = tid >> 5;
    const int wm = wid & 1, wn = wid >> 1;
    const int e  = blockIdx.z;
    const int me = g_ecount[e];
    const int m0 = blockIdx.y * 128;
    if (m0 >= me) return;
    const int n0 = blockIdx.x * 128;
    const int roff = g_offsets[e];
    const uint32_t smb = smem_u32(sm);

    int*   toks = (int*)sm;
    float* wro  = (float*)(sm + 512);
    if (tid < 128) {
        int m = m0 + tid;
        bool v = m < me;
        toks[tid] = v ? g_row_token[roff + m] : 0;
        wro[tid]  = v ? g_row_weight[roff + m] : 0.f;
    }
    __syncthreads();

    const int lr = tid >> 1, kseg = (tid & 1) * 16;
    const uint32_t soff = (uint32_t)(lr * STRIDE + kseg * 2);
    int mm = m0 + lr;
    size_t arow = (size_t)(roff + ((mm < me) ? mm : (me - 1)));
    const __half* axh = g_hb_h + arow * FDIM + kseg;
    const __half* axl = g_hb_l + arow * FDIM + kseg;
    const float* bp = w2 + ((size_t)e * HDIM + n0 + lr) * FDIM + kseg;

    float acc[4][4][4];
#pragma unroll
    for (int i = 0; i < 4; i++)
#pragma unroll
        for (int j = 0; j < 4; j++)
#pragma unroll
            for (int k = 0; k < 4; k++) acc[i][j][k] = 0.f;

    cpA(smb + toff(0, 0) + soff, axh, smb + toff(0, 1) + soff, axl);
    {
        float rb[16];
        ldg16f(rb, bp);
        sts_h16(sm + toff(0, 2) + soff, rb);
    }
    CP_COMMIT();
    float rbn[16];
    ldg16f(rbn, bp + 32);

    int buf = 0;
    const int NCH = FDIM / 32;
    for (int ch = 0; ch < NCH; ch++) {
        if (ch + 1 < NCH) {
            int k0 = (ch + 1) * 32;
            cpA(smb + toff(buf ^ 1, 0) + soff, axh + k0, smb + toff(buf ^ 1, 1) + soff, axl + k0);
            sts_h16(sm + toff(buf ^ 1, 2) + soff, rbn);
            CP_COMMIT(); CP_WAIT1();
            if (ch + 2 < NCH) ldg16f(rbn, bp + (ch + 2) * 32);
        } else CP_WAIT0();
        __syncthreads();
        mma_tile(acc, smb, buf, wm, wn, lane);
        __syncthreads();
        buf ^= 1;
    }

#pragma unroll
    for (int mi = 0; mi < 4; mi++) {
        int lrow = wm * 64 + mi * 16 + (lane >> 2);
        int r = m0 + lrow;
        int t0 = toks[lrow], t1 = toks[lrow + 8];
        float w0 = wro[lrow], w1v = wro[lrow + 8];
#pragma unroll
        for (int ni = 0; ni < 4; ni++) {
            int col = n0 + wn * 32 + ni * 8 + 2 * (lane & 3);
            float* d = acc[mi][ni];
            if (r < me) {
                atomicAdd(out + (size_t)t0 * HDIM + col,     d[0] * w0);
                atomicAdd(out + (size_t)t0 * HDIM + col + 1, d[1] * w0);
            }
            if (r + 8 < me) {
                atomicAdd(out + (size_t)t1 * HDIM + col,     d[2] * w1v);
                atomicAdd(out + (size_t)t1 * HDIM + col + 1, d[3] * w1v);
            }
        }
    }
}

// =====================================================================
// Shared GEMM1: x planes @ interleaved(sg,su) plane -> SwiGLU -> hs planes
// =====================================================================
__global__ void __launch_bounds__(256, 2) sg1_kernel() {
    extern __shared__ char sm[];
    const int tid = threadIdx.x, lane = tid & 31, wid = tid >> 5;
    const int wm = wid & 1, wn = wid >> 1;
    const int m0 = blockIdx.y * 128;
    const int f0 = blockIdx.x * 64;
    const uint32_t smb = smem_u32(sm);

    const int lr = tid >> 1, kseg = (tid & 1) * 16;
    const uint32_t soff = (uint32_t)(lr * STRIDE + kseg * 2);
    const __half* axh = g_x_h + (size_t)(m0 + lr) * HDIM + kseg;
    const __half* axl = g_x_l + (size_t)(m0 + lr) * HDIM + kseg;
    const __half* bxh = ((lr & 1) ? g_su_h : g_sg_h) + (size_t)(f0 + (lr >> 1)) * HDIM + kseg;

    float acc[4][4][4];
#pragma unroll
    for (int i = 0; i < 4; i++)
#pragma unroll
        for (int j = 0; j < 4; j++)
#pragma unroll
            for (int k = 0; k < 4; k++) acc[i][j][k] = 0.f;

    cpA(smb + toff(0, 0) + soff, axh, smb + toff(0, 1) + soff, axl);
    CP16(smb + toff(0, 2) + soff, bxh); CP16(smb + toff(0, 2) + soff + 16, bxh + 8);
    CP_COMMIT();

    int buf = 0;
    const int NCH = HDIM / 32;
    for (int ch = 0; ch < NCH; ch++) {
        if (ch + 1 < NCH) {
            int k0 = (ch + 1) * 32;
            cpA(smb + toff(buf ^ 1, 0) + soff, axh + k0, smb + toff(buf ^ 1, 1) + soff, axl + k0);
            CP16(smb + toff(buf ^ 1, 2) + soff, bxh + k0);
            CP16(smb + toff(buf ^ 1, 2) + soff + 16, bxh + k0 + 8);
            CP_COMMIT(); CP_WAIT1();
        } else CP_WAIT0();
        __syncthreads();
        mma_tile(acc, smb, buf, wm, wn, lane);
        __syncthreads();
        buf ^= 1;
    }

#pragma unroll
    for (int mi = 0; mi < 4; mi++) {
        int r = m0 + wm * 64 + mi * 16 + (lane >> 2);
#pragma unroll
        for (int ni = 0; ni < 4; ni++) {
            int lc = f0 + wn * 16 + ni * 4 + (lane & 3);
            float* d = acc[mi][ni];
            size_t o0 = (size_t)r * F2DIM + lc;
            size_t o1 = (size_t)(r + 8) * F2DIM + lc;
            store_h2(g_hs_h + o0, g_hs_l + o0, silu_mul(d[0], d[1]));
            store_h2(g_hs_h + o1, g_hs_l + o1, silu_mul(d[2], d[3]));
        }
    }
}

// =====================================================================
// Shared GEMM2: hs planes @ sd plane -> overwrite out
// =====================================================================
__global__ void __launch_bounds__(256, 2) sg2_kernel(float* __restrict__ out) {
    extern __shared__ char sm[];
    const int tid = threadIdx.x, lane = tid & 31, wid = tid >> 5;
    const int wm = wid & 1, wn = wid >> 1;
    const int m0 = blockIdx.y * 128;
    const int n0 = blockIdx.x * 128;
    const uint32_t smb = smem_u32(sm);

    const int lr = tid >> 1, kseg = (tid & 1) * 16;
    const uint32_t soff = (uint32_t)(lr * STRIDE + kseg * 2);
    const __half* axh = g_hs_h + (size_t)(m0 + lr) * F2DIM + kseg;
    const __half* axl = g_hs_l + (size_t)(m0 + lr) * F2DIM + kseg;
    const __half* bxh = g_sd_h + (size_t)(n0 + lr) * F2DIM + kseg;

    float acc[4][4][4];
#pragma unroll
    for (int i = 0; i < 4; i++)
#pragma unroll
        for (int j = 0; j < 4; j++)
#pragma unroll
            for (int k = 0; k < 4; k++) acc[i][j][k] = 0.f;

    cpA(smb + toff(0, 0) + soff, axh, smb + toff(0, 1) + soff, axl);
    CP16(smb + toff(0, 2) + soff, bxh); CP16(smb + toff(0, 2) + soff + 16, bxh + 8);
    CP_COMMIT();

    int buf = 0;
    const int NCH = F2DIM / 32;
    for (int ch = 0; ch < NCH; ch++) {
        if (ch + 1 < NCH) {
            int k0 = (ch + 1) * 32;
            cpA(smb + toff(buf ^ 1, 0) + soff, axh + k0, smb + toff(buf ^ 1, 1) + soff, axl + k0);
            CP16(smb + toff(buf ^ 1, 2) + soff, bxh + k0);
            CP16(smb + toff(buf ^ 1, 2) + soff + 16, bxh + k0 + 8);
            CP_COMMIT(); CP_WAIT1();
        } else CP_WAIT0();
        __syncthreads();
        mma_tile(acc, smb, buf, wm, wn, lane);
        __syncthreads();
        buf ^= 1;
    }

#pragma unroll
    for (int mi = 0; mi < 4; mi++) {
        int r = m0 + wm * 64 + mi * 16 + (lane >> 2);
#pragma unroll
        for (int ni = 0; ni < 4; ni++) {
            int col = n0 + wn * 32 + ni * 8 + 2 * (lane & 3);
            float* d = acc[mi][ni];
            *(float2*)(out + (size_t)r * HDIM + col)       = make_float2(d[0], d[1]);
            *(float2*)(out + (size_t)(r + 8) * HDIM + col) = make_float2(d[2], d[3]);
        }
    }
}

// ---------------- launch ----------------
extern "C" void kernel_launch(void* const* d_in, const int* in_sizes, int n_in,
                              void* d_out, int out_size) {
    const float* x   = (const float*)d_in[0];
    const float* gw  = (const float*)d_in[1];
    const float* eb  = (const float*)d_in[2];
    const float* w1  = (const float*)d_in[3];
    const float* w2  = (const float*)d_in[4];
    const float* w3  = (const float*)d_in[5];
    const float* sg  = (const float*)d_in[6];
    const float* su  = (const float*)d_in[7];
    const float* sd  = (const float*)d_in[8];
    float* out = (float*)d_out;

    static bool init_done = false;
    static __half *pxh, *pxl, *psgh, *psuh, *psdh;
    if (!init_done) {
        cudaFuncSetAttribute(eg1_kernel, cudaFuncAttributeMaxDynamicSharedMemorySize, SMEM_SZ);
        cudaFuncSetAttribute(eg2_kernel, cudaFuncAttributeMaxDynamicSharedMemorySize, SMEM_SZ);
        cudaFuncSetAttribute(sg1_kernel, cudaFuncAttributeMaxDynamicSharedMemorySize, SMEM_SZ);
        cudaFuncSetAttribute(sg2_kernel, cudaFuncAttributeMaxDynamicSharedMemorySize, SMEM_SZ);
        cudaGetSymbolAddress((void**)&pxh,  g_x_h);  cudaGetSymbolAddress((void**)&pxl, g_x_l);
        cudaGetSymbolAddress((void**)&psgh, g_sg_h); cudaGetSymbolAddress((void**)&psuh, g_su_h);
        cudaGetSymbolAddress((void**)&psdh, g_sd_h);
        init_done = true;
    }

    // presplit activations (2-plane) and shared weights (1-plane)
    split2_kernel<<<TOK * HDIM / 8 / 256, 256>>>(x, pxh, pxl);
    split1_kernel<<<F2DIM * HDIM / 8 / 256, 256>>>(sg, psgh);
    split1_kernel<<<F2DIM * HDIM / 8 / 256, 256>>>(su, psuh);
    split1_kernel<<<HDIM * F2DIM / 8 / 256, 256>>>(sd, psdh);

    init_kernel<<<1, 64>>>();
    route_kernel<<<TOK, 256>>>(x, gw, eb);
    scan_kernel<<<1, 32>>>();
    assign_kernel<<<SKTOT / 256, 256>>>();

    // expert up-proj + SwiGLU -> hbuf planes
    eg1_kernel<<<dim3(FDIM / 64, CAPE / 128, NEXP), 256, SMEM_SZ>>>(w1, w3);

    // shared expert: sg1 -> hs planes, sg2 overwrites out
    sg1_kernel<<<dim3(F2DIM / 64, TOK / 128), 256, SMEM_SZ>>>();
    sg2_kernel<<<dim3(HDIM / 128, TOK / 128), 256, SMEM_SZ>>>(out);

    // expert down-proj + weighted scatter-add
    eg2_kernel<<<dim3(HDIM / 128, CAPE / 128, NEXP), 256, SMEM_SZ>>>(w2, out);
}

// round 8
// speedup vs baseline: 1.6478x; 1.1211x over previous
#include <cuda_runtime.h>
#include <cuda_fp16.h>
#include <math.h>
#include <stdint.h>

// ---------------- problem constants ----------------
#define TOK     2048
#define HDIM    1024
#define FDIM    512
#define F2DIM   1024
#define NEXP    64
#define TOPK    8
#define NGRP    8
#define TGRP    4
#define CAPE    1024
#define SKTOT   (TOK*TOPK)
#define SCALE   2.5f

// ---------------- device scratch: fp16 planes ----------------
__device__ __half g_x_h[TOK * HDIM];
__device__ __half g_x_l[TOK * HDIM];
__device__ __half g_sg_h[F2DIM * HDIM];
__device__ __half g_su_h[F2DIM * HDIM];
__device__ __half g_sd_h[HDIM * F2DIM];
__device__ __half g_hb_h[SKTOT * FDIM];
__device__ __half g_hs_h[TOK * F2DIM];
__device__ int   g_topk_idx[SKTOT];
__device__ float g_topk_w[SKTOT];
__device__ int   g_counts[NEXP];
__device__ int   g_fill[NEXP];
__device__ int   g_offsets[NEXP];
__device__ int   g_ecount[NEXP];
__device__ int   g_row_token[SKTOT];
__device__ float g_row_weight[SKTOT];

// ---------------- helpers ----------------
__device__ __forceinline__ float silu_mul(float g, float u) {
    return g / (1.f + expf(-g)) * u;
}
__device__ __forceinline__ uint32_t smem_u32(const void* p) {
    uint32_t a;
    asm("{ .reg .u64 t; cvta.to.shared.u64 t, %1; cvt.u32.u64 %0, t; }" : "=r"(a) : "l"(p));
    return a;
}
// pack rn-fp16 of (a,b): low half = a
__device__ __forceinline__ uint32_t h_pair(float a, float b) {
    uint32_t r;
    asm("cvt.rn.f16x2.f32 %0, %1, %2;" : "=r"(r) : "f"(b), "f"(a));
    return r;
}

// ---------------- mma.sync / ldmatrix / cp.async primitives ----------------
__device__ __forceinline__ void ldsm4(uint32_t* r, uint32_t a) {
    asm volatile("ldmatrix.sync.aligned.m8n8.x4.shared.b16 {%0,%1,%2,%3}, [%4];"
                 : "=r"(r[0]), "=r"(r[1]), "=r"(r[2]), "=r"(r[3]) : "r"(a));
}
__device__ __forceinline__ void mma_f16(float* d, const uint32_t* a, const uint32_t* b) {
    asm volatile("mma.sync.aligned.m16n8k16.row.col.f32.f16.f16.f32 "
                 "{%0,%1,%2,%3}, {%4,%5,%6,%7}, {%8,%9}, {%0,%1,%2,%3};"
                 : "+f"(d[0]), "+f"(d[1]), "+f"(d[2]), "+f"(d[3])
                 : "r"(a[0]), "r"(a[1]), "r"(a[2]), "r"(a[3]), "r"(b[0]), "r"(b[1]));
}
#define CP16(dst, src) \
    asm volatile("cp.async.cg.shared.global [%0], [%1], 16;" :: "r"(dst), "l"(src))
#define CP_COMMIT() asm volatile("cp.async.commit_group;" ::: "memory")
#define CP_WAIT1()  asm volatile("cp.async.wait_group 1;" ::: "memory")
#define CP_WAIT0()  asm volatile("cp.async.wait_group 0;" ::: "memory")

// ---------------- SMEM tile layout ----------------
// each plane: 128 rows x 32 fp16, row stride 80B
#define STRIDE   80
#define PLANE    10240
#define SM_TILES 1024
#define SMEM_SZ3 (SM_TILES + 6 * PLANE)   // 62464 : 3 planes x 2 bufs (eg1/sg1)
#define SMEM_SZ2 (SM_TILES + 4 * PLANE)   // 41984 : 2 planes x 2 bufs (eg2/sg2)

__device__ __forceinline__ uint32_t toff3(int buf, int p) {
    return SM_TILES + (uint32_t)(buf * 3 + p) * PLANE;
}
__device__ __forceinline__ uint32_t toff2(int buf, int p) {
    return SM_TILES + (uint32_t)(buf * 2 + p) * PLANE;
}

// 2-product chunk: acc += Ah*B + Al*B   (planes: 0=A_hi 1=A_lo 2=B)
__device__ __forceinline__ void mma_tile2(float (&acc)[4][4][4], uint32_t smb, int buf,
                                          int wm, int wn, int lane) {
    const uint32_t base = smb + SM_TILES + (uint32_t)buf * 3 * PLANE;
    const uint32_t la = base + (uint32_t)((wm * 64 + (lane & 15)) * STRIDE) + (uint32_t)((lane >> 4) << 4);
    const uint32_t lb = base + 2 * PLANE + ((lane & 16) ? 8 * STRIDE : 0)
                        + (uint32_t)((wn * 32 + (lane & 7)) * STRIDE)
                        + (uint32_t)(((lane >> 3) & 1) << 4);
#pragma unroll
    for (int ks = 0; ks < 2; ks++) {
        const int ko = ks * 32;
        uint32_t ah[4][4], al_[4][4], bf[2][4];
#pragma unroll
        for (int mi = 0; mi < 4; mi++) ldsm4(ah[mi], la + mi * 16 * STRIDE + ko);
#pragma unroll
        for (int mi = 0; mi < 4; mi++) ldsm4(al_[mi], la + PLANE + mi * 16 * STRIDE + ko);
        ldsm4(bf[0], lb + ko);
        ldsm4(bf[1], lb + 16 * STRIDE + ko);
#pragma unroll
        for (int mi = 0; mi < 4; mi++)
#pragma unroll
            for (int ni = 0; ni < 4; ni++) {
                const uint32_t* b = &bf[ni >> 1][(ni & 1) * 2];
                mma_f16(acc[mi][ni], ah[mi], b);
                mma_f16(acc[mi][ni], al_[mi], b);
            }
    }
}

// 1-product chunk: acc += A*B   (planes: 0=A 1=B)
__device__ __forceinline__ void mma_tile1(float (&acc)[4][4][4], uint32_t smb, int buf,
                                          int wm, int wn, int lane) {
    const uint32_t base = smb + SM_TILES + (uint32_t)buf * 2 * PLANE;
    const uint32_t la = base + (uint32_t)((wm * 64 + (lane & 15)) * STRIDE) + (uint32_t)((lane >> 4) << 4);
    const uint32_t lb = base + PLANE + ((lane & 16) ? 8 * STRIDE : 0)
                        + (uint32_t)((wn * 32 + (lane & 7)) * STRIDE)
                        + (uint32_t)(((lane >> 3) & 1) << 4);
#pragma unroll
    for (int ks = 0; ks < 2; ks++) {
        const int ko = ks * 32;
        uint32_t ah[4][4], bf[2][4];
#pragma unroll
        for (int mi = 0; mi < 4; mi++) ldsm4(ah[mi], la + mi * 16 * STRIDE + ko);
        ldsm4(bf[0], lb + ko);
        ldsm4(bf[1], lb + 16 * STRIDE + ko);
#pragma unroll
        for (int mi = 0; mi < 4; mi++)
#pragma unroll
            for (int ni = 0; ni < 4; ni++)
                mma_f16(acc[mi][ni], ah[mi], &bf[ni >> 1][(ni & 1) * 2]);
    }
}

// ---------------- loaders ----------------
__device__ __forceinline__ void ldg16f(float* r, const float* __restrict__ p) {
#pragma unroll
    for (int i = 0; i < 4; i++) *(float4*)(r + i * 4) = *(const float4*)(p + i * 4);
}
__device__ __forceinline__ void sts_h16(char* p, const float* v) {
    uint4 H0, H1;
    H0.x = h_pair(v[0], v[1]);   H0.y = h_pair(v[2], v[3]);
    H0.z = h_pair(v[4], v[5]);   H0.w = h_pair(v[6], v[7]);
    H1.x = h_pair(v[8], v[9]);   H1.y = h_pair(v[10], v[11]);
    H1.z = h_pair(v[12], v[13]); H1.w = h_pair(v[14], v[15]);
    *(uint4*)p = H0; *(uint4*)(p + 16) = H1;
}
__device__ __forceinline__ void cp32B(uint32_t d, const __half* s) {
    CP16(d, s); CP16(d + 16, s + 8);
}

// ---------------- presplit kernels ----------------
__global__ __launch_bounds__(256) void split2_kernel(const float* __restrict__ s,
                                                     __half* __restrict__ hq,
                                                     __half* __restrict__ lq) {
    int i = blockIdx.x * blockDim.x + threadIdx.x;
    const float4* p = (const float4*)s + (size_t)i * 2;
    float4 v0 = p[0], v1 = p[1];
    float vv[8] = {v0.x, v0.y, v0.z, v0.w, v1.x, v1.y, v1.z, v1.w};
    uint4 H, L;
    uint32_t* hp = (uint32_t*)&H;
    uint32_t* lp = (uint32_t*)&L;
#pragma unroll
    for (int j = 0; j < 4; j++) {
        __half2 h = __floats2half2_rn(vv[2 * j], vv[2 * j + 1]);
        float2 bk = __half22float2(h);
        __half2 l = __floats2half2_rn(vv[2 * j] - bk.x, vv[2 * j + 1] - bk.y);
        hp[j] = *(uint32_t*)&h;
        lp[j] = *(uint32_t*)&l;
    }
    ((uint4*)hq)[i] = H;
    ((uint4*)lq)[i] = L;
}
// fused 1-plane split of the three shared-expert weights (same size each)
__global__ __launch_bounds__(256) void split1x3_kernel(const float* __restrict__ s0,
                                                       const float* __restrict__ s1,
                                                       const float* __restrict__ s2,
                                                       __half* __restrict__ h0,
                                                       __half* __restrict__ h1,
                                                       __half* __restrict__ h2) {
    int i = blockIdx.x * blockDim.x + threadIdx.x;
    const float* s = (blockIdx.y == 0) ? s0 : (blockIdx.y == 1) ? s1 : s2;
    __half* hq     = (blockIdx.y == 0) ? h0 : (blockIdx.y == 1) ? h1 : h2;
    const float4* p = (const float4*)s + (size_t)i * 2;
    float4 v0 = p[0], v1 = p[1];
    uint4 H;
    H.x = h_pair(v0.x, v0.y); H.y = h_pair(v0.z, v0.w);
    H.z = h_pair(v1.x, v1.y); H.w = h_pair(v1.z, v1.w);
    ((uint4*)hq)[i] = H;
}

// ---------------- init ----------------
__global__ void init_kernel() {
    int i = threadIdx.x;
    if (i < NEXP) { g_counts[i] = 0; g_fill[i] = 0; }
}

// ---------------- routing ----------------
__global__ __launch_bounds__(256) void route_kernel(const float* __restrict__ x,
                                                    const float* __restrict__ gw,
                                                    const float* __restrict__ eb) {
    const int t = blockIdx.x;
    __shared__ float xs[HDIM];
    __shared__ float sc[NEXP];
    __shared__ float sfc[NEXP];
    const int tid = threadIdx.x;
    const float* xr = x + (size_t)t * HDIM;
    #pragma unroll
    for (int i = 0; i < HDIM / 256; i++) xs[tid + i * 256] = xr[tid + i * 256];
    __syncthreads();

    const int warp = tid >> 5, lane = tid & 31;
    for (int q = 0; q < NEXP / 8; q++) {
        const int e = warp * 8 + q;
        const float* gwe = gw + (size_t)e * HDIM;
        float s = 0.f;
        #pragma unroll
        for (int i = 0; i < HDIM / 32; i++)
            s = fmaf(xs[i * 32 + lane], gwe[i * 32 + lane], s);
        #pragma unroll
        for (int off = 16; off; off >>= 1) s += __shfl_down_sync(0xffffffffu, s, off);
        if (lane == 0) {
            float sig = 1.f / (1.f + expf(-s));
            sc[e] = sig;
            sfc[e] = sig + eb[e];
        }
    }
    __syncthreads();

    if (tid == 0) {
        float gsc[NGRP];
        #pragma unroll
        for (int g = 0; g < NGRP; g++) {
            float m1 = -1e30f, m2 = -1e30f;
            #pragma unroll
            for (int j = 0; j < NEXP / NGRP; j++) {
                float v = sfc[g * (NEXP / NGRP) + j];
                if (v > m1) { m2 = m1; m1 = v; } else if (v > m2) { m2 = v; }
            }
            gsc[g] = m1 + m2;
        }
        bool gsel[NGRP];
        #pragma unroll
        for (int g = 0; g < NGRP; g++) gsel[g] = false;
        for (int it = 0; it < TGRP; it++) {
            float best = -1e30f; int bi = 0;
            #pragma unroll
            for (int g = 0; g < NGRP; g++)
                if (!gsel[g] && gsc[g] > best) { best = gsc[g]; bi = g; }
            gsel[bi] = true;
        }
        float tmp[NEXP];
        #pragma unroll
        for (int e = 0; e < NEXP; e++)
            tmp[e] = gsel[e / (NEXP / NGRP)] ? sfc[e] : 0.0f;
        int   idx[TOPK];
        float wv[TOPK];
        float wsum = 0.f;
        for (int k = 0; k < TOPK; k++) {
            float best = -1e30f; int bi = 0;
            #pragma unroll
            for (int e = 0; e < NEXP; e++)
                if (tmp[e] > best) { best = tmp[e]; bi = e; }
            idx[k] = bi; tmp[bi] = -1e30f;
            wv[k] = sc[bi]; wsum += wv[k];
        }
        float inv = SCALE / (wsum + 1e-20f);
        for (int k = 0; k < TOPK; k++) {
            g_topk_idx[t * TOPK + k] = idx[k];
            g_topk_w[t * TOPK + k] = wv[k] * inv;
            atomicAdd(&g_counts[idx[k]], 1);
        }
    }
}

__global__ void scan_kernel() {
    if (threadIdx.x == 0) {
        int run = 0;
        for (int e = 0; e < NEXP; e++) {
            int c = g_counts[e];
            int cc = c < CAPE ? c : CAPE;
            g_offsets[e] = run;
            g_ecount[e] = cc;
            run += cc;
        }
    }
}

__global__ void assign_kernel() {
    int s = blockIdx.x * blockDim.x + threadIdx.x;
    if (s >= SKTOT) return;
    int e = g_topk_idx[s];
    int p = atomicAdd(&g_fill[e], 1);
    if (p < CAPE) {
        int r = g_offsets[e] + p;
        g_row_token[r] = s / TOPK;
        g_row_weight[r] = g_topk_w[s];
    }
}

// =====================================================================
// Expert GEMM1: x planes (2) @ interleaved(w1,w3) -> SwiGLU -> hbuf (1 plane)
// =====================================================================
__global__ void __launch_bounds__(256, 2) eg1_kernel(const float* __restrict__ w1,
                                                     const float* __restrict__ w3) {
    extern __shared__ char sm[];
    const int tid = threadIdx.x, lane = tid & 31, wid = tid >> 5;
    const int wm = wid & 1, wn = wid >> 1;
    const int e  = blockIdx.z;
    const int me = g_ecount[e];
    const int m0 = blockIdx.y * 128;
    if (m0 >= me) return;
    const int f0 = blockIdx.x * 64;
    const int roff = g_offsets[e];
    const uint32_t smb = smem_u32(sm);

    int* toks = (int*)sm;
    if (tid < 128) {
        int m = m0 + tid;
        toks[tid] = g_row_token[roff + ((m < me) ? m : 0)];
    }
    __syncthreads();

    const int lr = tid >> 1, kseg = (tid & 1) * 16;
    const uint32_t soff = (uint32_t)(lr * STRIDE + kseg * 2);
    const __half* axh = g_x_h + (size_t)toks[lr] * HDIM + kseg;
    const __half* axl = g_x_l + (size_t)toks[lr] * HDIM + kseg;
    const float* bp = ((lr & 1) ? w3 : w1) + ((size_t)e * FDIM + f0 + (lr >> 1)) * HDIM + kseg;

    float acc[4][4][4];
#pragma unroll
    for (int i = 0; i < 4; i++)
#pragma unroll
        for (int j = 0; j < 4; j++)
#pragma unroll
            for (int k = 0; k < 4; k++) acc[i][j][k] = 0.f;

    cp32B(smb + toff3(0, 0) + soff, axh);
    cp32B(smb + toff3(0, 1) + soff, axl);
    {
        float rb[16];
        ldg16f(rb, bp);
        sts_h16(sm + toff3(0, 2) + soff, rb);
    }
    CP_COMMIT();
    float rbn[16];
    ldg16f(rbn, bp + 32);

    int buf = 0;
    const int NCH = HDIM / 32;
    for (int ch = 0; ch < NCH; ch++) {
        if (ch + 1 < NCH) {
            int k0 = (ch + 1) * 32;
            cp32B(smb + toff3(buf ^ 1, 0) + soff, axh + k0);
            cp32B(smb + toff3(buf ^ 1, 1) + soff, axl + k0);
            sts_h16(sm + toff3(buf ^ 1, 2) + soff, rbn);
            CP_COMMIT(); CP_WAIT1();
            if (ch + 2 < NCH) ldg16f(rbn, bp + (ch + 2) * 32);
        } else CP_WAIT0();
        __syncthreads();
        mma_tile2(acc, smb, buf, wm, wn, lane);
        __syncthreads();
        buf ^= 1;
    }

#pragma unroll
    for (int mi = 0; mi < 4; mi++) {
        int r = m0 + wm * 64 + mi * 16 + (lane >> 2);
#pragma unroll
        for (int ni = 0; ni < 4; ni++) {
            int lc = f0 + wn * 16 + ni * 4 + (lane & 3);
            float* d = acc[mi][ni];
            if (r < me)
                g_hb_h[(size_t)(roff + r) * FDIM + lc] = __float2half_rn(silu_mul(d[0], d[1]));
            if (r + 8 < me)
                g_hb_h[(size_t)(roff + r + 8) * FDIM + lc] = __float2half_rn(silu_mul(d[2], d[3]));
        }
    }
}

// =====================================================================
// Expert GEMM2: hbuf (1 plane) @ w2 -> weighted atomicAdd into out
// =====================================================================
__global__ void __launch_bounds__(256, 2) eg2_kernel(const float* __restrict__ w2,
                                                     float* __restrict__ out) {
    extern __shared__ char sm[];
    const int tid = threadIdx.x, lane = tid & 31, wid = tid >> 5;
    const int wm = wid & 1, wn = wid >> 1;
    const int e  = blockIdx.z;
    const int me = g_ecount[e];
    const int m0 = blockIdx.y * 128;
    if (m0 >= me) return;
    const int n0 = blockIdx.x * 128;
    const int roff = g_offsets[e];
    const uint32_t smb = smem_u32(sm);

    int*   toks = (int*)sm;
    float* wro  = (float*)(sm + 512);
    if (tid < 128) {
        int m = m0 + tid;
        bool v = m < me;
        toks[tid] = v ? g_row_token[roff + m] : 0;
        wro[tid]  = v ? g_row_weight[roff + m] : 0.f;
    }
    __syncthreads();

    const int lr = tid >> 1, kseg = (tid & 1) * 16;
    const uint32_t soff = (uint32_t)(lr * STRIDE + kseg * 2);
    int mm = m0 + lr;
    size_t arow = (size_t)(roff + ((mm < me) ? mm : (me - 1)));
    const __half* axh = g_hb_h + arow * FDIM + kseg;
    const float* bp = w2 + ((size_t)e * HDIM + n0 + lr) * FDIM + kseg;

    float acc[4][4][4];
#pragma unroll
    for (int i = 0; i < 4; i++)
#pragma unroll
        for (int j = 0; j < 4; j++)
#pragma unroll
            for (int k = 0; k < 4; k++) acc[i][j][k] = 0.f;

    cp32B(smb + toff2(0, 0) + soff, axh);
    {
        float rb[16];
        ldg16f(rb, bp);
        sts_h16(sm + toff2(0, 1) + soff, rb);
    }
    CP_COMMIT();
    float rbn[16];
    ldg16f(rbn, bp + 32);

    int buf = 0;
    const int NCH = FDIM / 32;
    for (int ch = 0; ch < NCH; ch++) {
        if (ch + 1 < NCH) {
            int k0 = (ch + 1) * 32;
            cp32B(smb + toff2(buf ^ 1, 0) + soff, axh + k0);
            sts_h16(sm + toff2(buf ^ 1, 1) + soff, rbn);
            CP_COMMIT(); CP_WAIT1();
            if (ch + 2 < NCH) ldg16f(rbn, bp + (ch + 2) * 32);
        } else CP_WAIT0();
        __syncthreads();
        mma_tile1(acc, smb, buf, wm, wn, lane);
        __syncthreads();
        buf ^= 1;
    }

#pragma unroll
    for (int mi = 0; mi < 4; mi++) {
        int lrow = wm * 64 + mi * 16 + (lane >> 2);
        int r = m0 + lrow;
        int t0 = toks[lrow], t1 = toks[lrow + 8];
        float w0 = wro[lrow], w1v = wro[lrow + 8];
#pragma unroll
        for (int ni = 0; ni < 4; ni++) {
            int col = n0 + wn * 32 + ni * 8 + 2 * (lane & 3);
            float* d = acc[mi][ni];
            if (r < me) {
                atomicAdd(out + (size_t)t0 * HDIM + col,     d[0] * w0);
                atomicAdd(out + (size_t)t0 * HDIM + col + 1, d[1] * w0);
            }
            if (r + 8 < me) {
                atomicAdd(out + (size_t)t1 * HDIM + col,     d[2] * w1v);
                atomicAdd(out + (size_t)t1 * HDIM + col + 1, d[3] * w1v);
            }
        }
    }
}

// =====================================================================
// Shared GEMM1: x planes @ interleaved(sg,su) plane -> SwiGLU -> hs (1 plane)
// =====================================================================
__global__ void __launch_bounds__(256, 2) sg1_kernel() {
    extern __shared__ char sm[];
    const int tid = threadIdx.x, lane = tid & 31, wid = tid >> 5;
    const int wm = wid & 1, wn = wid >> 1;
    const int m0 = blockIdx.y * 128;
    const int f0 = blockIdx.x * 64;
    const uint32_t smb = smem_u32(sm);

    const int lr = tid >> 1, kseg = (tid & 1) * 16;
    const uint32_t soff = (uint32_t)(lr * STRIDE + kseg * 2);
    const __half* axh = g_x_h + (size_t)(m0 + lr) * HDIM + kseg;
    const __half* axl = g_x_l + (size_t)(m0 + lr) * HDIM + kseg;
    const __half* bxh = ((lr & 1) ? g_su_h : g_sg_h) + (size_t)(f0 + (lr >> 1)) * HDIM + kseg;

    float acc[4][4][4];
#pragma unroll
    for (int i = 0; i < 4; i++)
#pragma unroll
        for (int j = 0; j < 4; j++)
#pragma unroll
            for (int k = 0; k < 4; k++) acc[i][j][k] = 0.f;

    cp32B(smb + toff3(0, 0) + soff, axh);
    cp32B(smb + toff3(0, 1) + soff, axl);
    cp32B(smb + toff3(0, 2) + soff, bxh);
    CP_COMMIT();

    int buf = 0;
    const int NCH = HDIM / 32;
    for (int ch = 0; ch < NCH; ch++) {
        if (ch + 1 < NCH) {
            int k0 = (ch + 1) * 32;
            cp32B(smb + toff3(buf ^ 1, 0) + soff, axh + k0);
            cp32B(smb + toff3(buf ^ 1, 1) + soff, axl + k0);
            cp32B(smb + toff3(buf ^ 1, 2) + soff, bxh + k0);
            CP_COMMIT(); CP_WAIT1();
        } else CP_WAIT0();
        __syncthreads();
        mma_tile2(acc, smb, buf, wm, wn, lane);
        __syncthreads();
        buf ^= 1;
    }

#pragma unroll
    for (int mi = 0; mi < 4; mi++) {
        int r = m0 + wm * 64 + mi * 16 + (lane >> 2);
#pragma unroll
        for (int ni = 0; ni < 4; ni++) {
            int lc = f0 + wn * 16 + ni * 4 + (lane & 3);
            float* d = acc[mi][ni];
            g_hs_h[(size_t)r * F2DIM + lc]       = __float2half_rn(silu_mul(d[0], d[1]));
            g_hs_h[(size_t)(r + 8) * F2DIM + lc] = __float2half_rn(silu_mul(d[2], d[3]));
        }
    }
}

// =====================================================================
// Shared GEMM2: hs (1 plane) @ sd plane -> overwrite out
// =====================================================================
__global__ void __launch_bounds__(256, 2) sg2_kernel(float* __restrict__ out) {
    extern __shared__ char sm[];
    const int tid = threadIdx.x, lane = tid & 31, wid = tid >> 5;
    const int wm = wid & 1, wn = wid >> 1;
    const int m0 = blockIdx.y * 128;
    const int n0 = blockIdx.x * 128;
    const uint32_t smb = smem_u32(sm);

    const int lr = tid >> 1, kseg = (tid & 1) * 16;
    const uint32_t soff = (uint32_t)(lr * STRIDE + kseg * 2);
    const __half* axh = g_hs_h + (size_t)(m0 + lr) * F2DIM + kseg;
    const __half* bxh = g_sd_h + (size_t)(n0 + lr) * F2DIM + kseg;

    float acc[4][4][4];
#pragma unroll
    for (int i = 0; i < 4; i++)
#pragma unroll
        for (int j = 0; j < 4; j++)
#pragma unroll
            for (int k = 0; k < 4; k++) acc[i][j][k] = 0.f;

    cp32B(smb + toff2(0, 0) + soff, axh);
    cp32B(smb + toff2(0, 1) + soff, bxh);
    CP_COMMIT();

    int buf = 0;
    const int NCH = F2DIM / 32;
    for (int ch = 0; ch < NCH; ch++) {
        if (ch + 1 < NCH) {
            int k0 = (ch + 1) * 32;
            cp32B(smb + toff2(buf ^ 1, 0) + soff, axh + k0);
            cp32B(smb + toff2(buf ^ 1, 1) + soff, bxh + k0);
            CP_COMMIT(); CP_WAIT1();
        } else CP_WAIT0();
        __syncthreads();
        mma_tile1(acc, smb, buf, wm, wn, lane);
        __syncthreads();
        buf ^= 1;
    }

#pragma unroll
    for (int mi = 0; mi < 4; mi++) {
        int r = m0 + wm * 64 + mi * 16 + (lane >> 2);
#pragma unroll
        for (int ni = 0; ni < 4; ni++) {
            int col = n0 + wn * 32 + ni * 8 + 2 * (lane & 3);
            float* d = acc[mi][ni];
            *(float2*)(out + (size_t)r * HDIM + col)       = make_float2(d[0], d[1]);
            *(float2*)(out + (size_t)(r + 8) * HDIM + col) = make_float2(d[2], d[3]);
        }
    }
}

// ---------------- launch ----------------
extern "C" void kernel_launch(void* const* d_in, const int* in_sizes, int n_in,
                              void* d_out, int out_size) {
    const float* x   = (const float*)d_in[0];
    const float* gw  = (const float*)d_in[1];
    const float* eb  = (const float*)d_in[2];
    const float* w1  = (const float*)d_in[3];
    const float* w2  = (const float*)d_in[4];
    const float* w3  = (const float*)d_in[5];
    const float* sg  = (const float*)d_in[6];
    const float* su  = (const float*)d_in[7];
    const float* sd  = (const float*)d_in[8];
    float* out = (float*)d_out;

    static bool init_done = false;
    static __half *pxh, *pxl, *psgh, *psuh, *psdh;
    if (!init_done) {
        cudaFuncSetAttribute(eg1_kernel, cudaFuncAttributeMaxDynamicSharedMemorySize, SMEM_SZ3);
        cudaFuncSetAttribute(sg1_kernel, cudaFuncAttributeMaxDynamicSharedMemorySize, SMEM_SZ3);
        cudaFuncSetAttribute(eg2_kernel, cudaFuncAttributeMaxDynamicSharedMemorySize, SMEM_SZ2);
        cudaFuncSetAttribute(sg2_kernel, cudaFuncAttributeMaxDynamicSharedMemorySize, SMEM_SZ2);
        cudaGetSymbolAddress((void**)&pxh,  g_x_h);  cudaGetSymbolAddress((void**)&pxl, g_x_l);
        cudaGetSymbolAddress((void**)&psgh, g_sg_h); cudaGetSymbolAddress((void**)&psuh, g_su_h);
        cudaGetSymbolAddress((void**)&psdh, g_sd_h);
        init_done = true;
    }

    // presplit activations (2-plane) and shared weights (1-plane, fused)
    split2_kernel<<<TOK * HDIM / 8 / 256, 256>>>(x, pxh, pxl);
    split1x3_kernel<<<dim3(F2DIM * HDIM / 8 / 256, 3), 256>>>(sg, su, sd, psgh, psuh, psdh);

    init_kernel<<<1, 64>>>();
    route_kernel<<<TOK, 256>>>(x, gw, eb);
    scan_kernel<<<1, 32>>>();
    assign_kernel<<<SKTOT / 256, 256>>>();

    // expert up-proj + SwiGLU -> hbuf plane
    eg1_kernel<<<dim3(FDIM / 64, CAPE / 128, NEXP), 256, SMEM_SZ3>>>(w1, w3);

    // shared expert: sg1 -> hs plane, sg2 overwrites out
    sg1_kernel<<<dim3(F2DIM / 64, TOK / 128), 256, SMEM_SZ3>>>();
    sg2_kernel<<<dim3(HDIM / 128, TOK / 128), 256, SMEM_SZ2>>>(out);

    // expert down-proj + weighted scatter-add
    eg2_kernel<<<dim3(HDIM / 128, CAPE / 128, NEXP), 256, SMEM_SZ2>>>(w2, out);
}

// round 9
// speedup vs baseline: 1.6916x; 1.0266x over previous
#include <cuda_runtime.h>
#include <cuda_fp16.h>
#include <math.h>
#include <stdint.h>

// ---------------- problem constants ----------------
#define TOK     2048
#define HDIM    1024
#define FDIM    512
#define F2DIM   1024
#define NEXP    64
#define TOPK    8
#define NGRP    8
#define TGRP    4
#define CAPE    1024
#define SKTOT   (TOK*TOPK)
#define SCALE   2.5f

// ---------------- device scratch ----------------
__device__ __half g_x_h[TOK * HDIM];
__device__ __half g_x_l[TOK * HDIM];
__device__ __half g_gw_h[NEXP * HDIM];
__device__ __half g_gw_l[NEXP * HDIM];
__device__ __half g_sg_h[F2DIM * HDIM];
__device__ __half g_su_h[F2DIM * HDIM];
__device__ __half g_sd_h[HDIM * F2DIM];
__device__ __half g_hb_h[SKTOT * FDIM];
__device__ __half g_hs_h[TOK * F2DIM];
__device__ float g_logits[TOK * NEXP];
__device__ int   g_topk_idx[SKTOT];
__device__ float g_topk_w[SKTOT];
__device__ int   g_counts[NEXP];
__device__ int   g_fill[NEXP];
__device__ int   g_offsets[NEXP];
__device__ int   g_ecount[NEXP];
__device__ int   g_row_token[SKTOT];
__device__ float g_row_weight[SKTOT];

// ---------------- helpers ----------------
__device__ __forceinline__ float silu_mul(float g, float u) {
    return g / (1.f + expf(-g)) * u;
}
__device__ __forceinline__ uint32_t smem_u32(const void* p) {
    uint32_t a;
    asm("{ .reg .u64 t; cvta.to.shared.u64 t, %1; cvt.u32.u64 %0, t; }" : "=r"(a) : "l"(p));
    return a;
}
__device__ __forceinline__ uint32_t h_pair(float a, float b) {
    uint32_t r;
    asm("cvt.rn.f16x2.f32 %0, %1, %2;" : "=r"(r) : "f"(b), "f"(a));
    return r;
}

// ---------------- mma.sync / ldmatrix / cp.async primitives ----------------
__device__ __forceinline__ void ldsm4(uint32_t* r, uint32_t a) {
    asm volatile("ldmatrix.sync.aligned.m8n8.x4.shared.b16 {%0,%1,%2,%3}, [%4];"
                 : "=r"(r[0]), "=r"(r[1]), "=r"(r[2]), "=r"(r[3]) : "r"(a));
}
__device__ __forceinline__ void mma_f16(float* d, const uint32_t* a, const uint32_t* b) {
    asm volatile("mma.sync.aligned.m16n8k16.row.col.f32.f16.f16.f32 "
                 "{%0,%1,%2,%3}, {%4,%5,%6,%7}, {%8,%9}, {%0,%1,%2,%3};"
                 : "+f"(d[0]), "+f"(d[1]), "+f"(d[2]), "+f"(d[3])
                 : "r"(a[0]), "r"(a[1]), "r"(a[2]), "r"(a[3]), "r"(b[0]), "r"(b[1]));
}
#define CP16(dst, src) \
    asm volatile("cp.async.cg.shared.global [%0], [%1], 16;" :: "r"(dst), "l"(src))
#define CP_COMMIT() asm volatile("cp.async.commit_group;" ::: "memory")
#define CP_WAIT1()  asm volatile("cp.async.wait_group 1;" ::: "memory")
#define CP_WAIT0()  asm volatile("cp.async.wait_group 0;" ::: "memory")

// ---------------- SMEM tile layout ----------------
#define STRIDE   80
#define PLANE    10240
#define SM_TILES 1024
#define SMEM_SZ3 (SM_TILES + 6 * PLANE)   // 62464 : eg1/sg1 (and logits)
#define SMEM_SZ2 (SM_TILES + 4 * PLANE)   // 41984 : eg2/sg2

__device__ __forceinline__ uint32_t toff3(int buf, int p) {
    return SM_TILES + (uint32_t)(buf * 3 + p) * PLANE;
}
__device__ __forceinline__ uint32_t toff2(int buf, int p) {
    return SM_TILES + (uint32_t)(buf * 2 + p) * PLANE;
}

// 2-product chunk: acc += Ah*B + Al*B
__device__ __forceinline__ void mma_tile2(float (&acc)[4][4][4], uint32_t smb, int buf,
                                          int wm, int wn, int lane) {
    const uint32_t base = smb + SM_TILES + (uint32_t)buf * 3 * PLANE;
    const uint32_t la = base + (uint32_t)((wm * 64 + (lane & 15)) * STRIDE) + (uint32_t)((lane >> 4) << 4);
    const uint32_t lb = base + 2 * PLANE + ((lane & 16) ? 8 * STRIDE : 0)
                        + (uint32_t)((wn * 32 + (lane & 7)) * STRIDE)
                        + (uint32_t)(((lane >> 3) & 1) << 4);
#pragma unroll
    for (int ks = 0; ks < 2; ks++) {
        const int ko = ks * 32;
        uint32_t ah[4][4], al_[4][4], bf[2][4];
#pragma unroll
        for (int mi = 0; mi < 4; mi++) ldsm4(ah[mi], la + mi * 16 * STRIDE + ko);
#pragma unroll
        for (int mi = 0; mi < 4; mi++) ldsm4(al_[mi], la + PLANE + mi * 16 * STRIDE + ko);
        ldsm4(bf[0], lb + ko);
        ldsm4(bf[1], lb + 16 * STRIDE + ko);
#pragma unroll
        for (int mi = 0; mi < 4; mi++)
#pragma unroll
            for (int ni = 0; ni < 4; ni++) {
                const uint32_t* b = &bf[ni >> 1][(ni & 1) * 2];
                mma_f16(acc[mi][ni], ah[mi], b);
                mma_f16(acc[mi][ni], al_[mi], b);
            }
    }
}

// 1-product chunk: acc += A*B
__device__ __forceinline__ void mma_tile1(float (&acc)[4][4][4], uint32_t smb, int buf,
                                          int wm, int wn, int lane) {
    const uint32_t base = smb + SM_TILES + (uint32_t)buf * 2 * PLANE;
    const uint32_t la = base + (uint32_t)((wm * 64 + (lane & 15)) * STRIDE) + (uint32_t)((lane >> 4) << 4);
    const uint32_t lb = base + PLANE + ((lane & 16) ? 8 * STRIDE : 0)
                        + (uint32_t)((wn * 32 + (lane & 7)) * STRIDE)
                        + (uint32_t)(((lane >> 3) & 1) << 4);
#pragma unroll
    for (int ks = 0; ks < 2; ks++) {
        const int ko = ks * 32;
        uint32_t ah[4][4], bf[2][4];
#pragma unroll
        for (int mi = 0; mi < 4; mi++) ldsm4(ah[mi], la + mi * 16 * STRIDE + ko);
        ldsm4(bf[0], lb + ko);
        ldsm4(bf[1], lb + 16 * STRIDE + ko);
#pragma unroll
        for (int mi = 0; mi < 4; mi++)
#pragma unroll
            for (int ni = 0; ni < 4; ni++)
                mma_f16(acc[mi][ni], ah[mi], &bf[ni >> 1][(ni & 1) * 2]);
    }
}

// ---------------- loaders ----------------
__device__ __forceinline__ void ldg16f(float* r, const float* __restrict__ p) {
#pragma unroll
    for (int i = 0; i < 4; i++) *(float4*)(r + i * 4) = *(const float4*)(p + i * 4);
}
__device__ __forceinline__ void sts_h16(char* p, const float* v) {
    uint4 H0, H1;
    H0.x = h_pair(v[0], v[1]);   H0.y = h_pair(v[2], v[3]);
    H0.z = h_pair(v[4], v[5]);   H0.w = h_pair(v[6], v[7]);
    H1.x = h_pair(v[8], v[9]);   H1.y = h_pair(v[10], v[11]);
    H1.z = h_pair(v[12], v[13]); H1.w = h_pair(v[14], v[15]);
    *(uint4*)p = H0; *(uint4*)(p + 16) = H1;
}
__device__ __forceinline__ void cp32B(uint32_t d, const __half* s) {
    CP16(d, s); CP16(d + 16, s + 8);
}

// ---------------- presplit kernels ----------------
__global__ __launch_bounds__(256) void split2_kernel(const float* __restrict__ s,
                                                     __half* __restrict__ hq,
                                                     __half* __restrict__ lq) {
    int i = blockIdx.x * blockDim.x + threadIdx.x;
    const float4* p = (const float4*)s + (size_t)i * 2;
    float4 v0 = p[0], v1 = p[1];
    float vv[8] = {v0.x, v0.y, v0.z, v0.w, v1.x, v1.y, v1.z, v1.w};
    uint4 H, L;
    uint32_t* hp = (uint32_t*)&H;
    uint32_t* lp = (uint32_t*)&L;
#pragma unroll
    for (int j = 0; j < 4; j++) {
        __half2 h = __floats2half2_rn(vv[2 * j], vv[2 * j + 1]);
        float2 bk = __half22float2(h);
        __half2 l = __floats2half2_rn(vv[2 * j] - bk.x, vv[2 * j + 1] - bk.y);
        hp[j] = *(uint32_t*)&h;
        lp[j] = *(uint32_t*)&l;
    }
    ((uint4*)hq)[i] = H;
    ((uint4*)lq)[i] = L;
}
__global__ __launch_bounds__(256) void split1x3_kernel(const float* __restrict__ s0,
                                                       const float* __restrict__ s1,
                                                       const float* __restrict__ s2,
                                                       __half* __restrict__ h0,
                                                       __half* __restrict__ h1,
                                                       __half* __restrict__ h2) {
    int i = blockIdx.x * blockDim.x + threadIdx.x;
    const float* s = (blockIdx.y == 0) ? s0 : (blockIdx.y == 1) ? s1 : s2;
    __half* hq     = (blockIdx.y == 0) ? h0 : (blockIdx.y == 1) ? h1 : h2;
    const float4* p = (const float4*)s + (size_t)i * 2;
    float4 v0 = p[0], v1 = p[1];
    uint4 H;
    H.x = h_pair(v0.x, v0.y); H.y = h_pair(v0.z, v0.w);
    H.z = h_pair(v1.x, v1.y); H.w = h_pair(v1.z, v1.w);
    ((uint4*)hq)[i] = H;
}

// ---------------- init ----------------
__global__ void init_kernel() {
    int i = threadIdx.x;
    if (i < NEXP) { g_counts[i] = 0; g_fill[i] = 0; }
}

// =====================================================================
// logits: x planes @ gw planes (3-product) -> g_logits [TOK,64] fp32
// block: 128 tokens x 64 experts, K=1024 in 32-chunks
// smem per buf: AH(10240) AL(10240) BH(5120) BL(5120) = 30720
// =====================================================================
__global__ void __launch_bounds__(256, 2) logits_kernel() {
    extern __shared__ char sm[];
    const int tid = threadIdx.x, lane = tid & 31, wid = tid >> 5;
    const int wm = wid & 1, wn = wid >> 1;   // wn 0..3 -> 16 experts each
    const int m0 = blockIdx.x * 128;
    const uint32_t smb = smem_u32(sm);

    const int lr = tid >> 1, kseg = (tid & 1) * 16;
    const uint32_t soffA = (uint32_t)(lr * STRIDE + kseg * 2);
    const __half* axh = g_x_h + (size_t)(m0 + lr) * HDIM + kseg;
    const __half* axl = g_x_l + (size_t)(m0 + lr) * HDIM + kseg;
    const int br = tid >> 2, bks = (tid & 3) * 8;          // B: 64 rows x 4 x 8 fp16
    const uint32_t soffB = (uint32_t)(br * STRIDE + bks * 2);
    const __half* bgh = g_gw_h + (size_t)br * HDIM + bks;
    const __half* bgl = g_gw_l + (size_t)br * HDIM + bks;

    auto bufb = [&](int buf) { return smb + SM_TILES + (uint32_t)buf * 30720u; };

    float acc[4][2][4];
#pragma unroll
    for (int i = 0; i < 4; i++)
#pragma unroll
        for (int j = 0; j < 2; j++)
#pragma unroll
            for (int k = 0; k < 4; k++) acc[i][j][k] = 0.f;

    // prologue
    cp32B(bufb(0) + soffA, axh);
    cp32B(bufb(0) + 10240 + soffA, axl);
    CP16(bufb(0) + 20480 + soffB, bgh);
    CP16(bufb(0) + 25600 + soffB, bgl);
    CP_COMMIT();

    int buf = 0;
    const int NCH = HDIM / 32;
    for (int ch = 0; ch < NCH; ch++) {
        if (ch + 1 < NCH) {
            int k0 = (ch + 1) * 32;
            cp32B(bufb(buf ^ 1) + soffA, axh + k0);
            cp32B(bufb(buf ^ 1) + 10240 + soffA, axl + k0);
            CP16(bufb(buf ^ 1) + 20480 + soffB, bgh + k0);
            CP16(bufb(buf ^ 1) + 25600 + soffB, bgl + k0);
            CP_COMMIT(); CP_WAIT1();
        } else CP_WAIT0();
        __syncthreads();
        {
            const uint32_t base = bufb(buf);
            const uint32_t la = base + (uint32_t)((wm * 64 + (lane & 15)) * STRIDE) + (uint32_t)((lane >> 4) << 4);
            const uint32_t lb = base + 20480 + ((lane & 16) ? 8 * STRIDE : 0)
                                + (uint32_t)((wn * 16 + (lane & 7)) * STRIDE)
                                + (uint32_t)(((lane >> 3) & 1) << 4);
#pragma unroll
            for (int ks = 0; ks < 2; ks++) {
                const int ko = ks * 32;
                uint32_t ah[4][4], al_[4][4], bh[4], bl[4];
#pragma unroll
                for (int mi = 0; mi < 4; mi++) ldsm4(ah[mi], la + mi * 16 * STRIDE + ko);
#pragma unroll
                for (int mi = 0; mi < 4; mi++) ldsm4(al_[mi], la + 10240 + mi * 16 * STRIDE + ko);
                ldsm4(bh, lb + ko);
                ldsm4(bl, lb + 5120 + ko);
#pragma unroll
                for (int mi = 0; mi < 4; mi++)
#pragma unroll
                    for (int ni = 0; ni < 2; ni++) {
                        mma_f16(acc[mi][ni], ah[mi],  &bh[ni * 2]);
                        mma_f16(acc[mi][ni], al_[mi], &bh[ni * 2]);
                        mma_f16(acc[mi][ni], ah[mi],  &bl[ni * 2]);
                    }
            }
        }
        __syncthreads();
        buf ^= 1;
    }

#pragma unroll
    for (int mi = 0; mi < 4; mi++) {
        int r = m0 + wm * 64 + mi * 16 + (lane >> 2);
#pragma unroll
        for (int ni = 0; ni < 2; ni++) {
            int col = wn * 16 + ni * 8 + 2 * (lane & 3);
            float* d = acc[mi][ni];
            *(float2*)(g_logits + (size_t)r * NEXP + col)       = make_float2(d[0], d[1]);
            *(float2*)(g_logits + (size_t)(r + 8) * NEXP + col) = make_float2(d[2], d[3]);
        }
    }
}

// =====================================================================
// topk: one warp per token; group-limited top-k, warp-parallel
// =====================================================================
__global__ __launch_bounds__(256) void topk_kernel(const float* __restrict__ eb) {
    const int lane = threadIdx.x & 31;
    const int t = blockIdx.x * 8 + (threadIdx.x >> 5);
    const unsigned FULL = 0xffffffffu;

    float l0 = g_logits[(size_t)t * NEXP + lane];
    float l1 = g_logits[(size_t)t * NEXP + 32 + lane];
    float s0 = 1.f / (1.f + expf(-l0));
    float s1 = 1.f / (1.f + expf(-l1));
    float f0 = s0 + eb[lane];
    float f1 = s1 + eb[lane + 32];

    // group top-2 sums within width-8 subgroups (xor butterfly)
    float m1a = f0, m2a = -1e30f, m1b = f1, m2b = -1e30f;
#pragma unroll
    for (int off = 4; off; off >>= 1) {
        float o1 = __shfl_xor_sync(FULL, m1a, off), o2 = __shfl_xor_sync(FULL, m2a, off);
        if (o1 >= m1a) { m2a = fmaxf(m1a, o2); m1a = o1; } else m2a = fmaxf(m2a, o1);
        float p1 = __shfl_xor_sync(FULL, m1b, off), p2 = __shfl_xor_sync(FULL, m2b, off);
        if (p1 >= m1b) { m2b = fmaxf(m1b, p2); m1b = p1; } else m2b = fmaxf(m2b, p1);
    }
    float g2lo = m1a + m2a;   // group (lane>>3)
    float g2hi = m1b + m2b;   // group 4 + (lane>>3)

    float gsc[NGRP];
#pragma unroll
    for (int g = 0; g < 4; g++) gsc[g]     = __shfl_sync(FULL, g2lo, g * 8);
#pragma unroll
    for (int g = 0; g < 4; g++) gsc[4 + g] = __shfl_sync(FULL, g2hi, g * 8);

    unsigned gsel = 0;
#pragma unroll
    for (int it = 0; it < TGRP; it++) {
        float best = -1e30f; int bi = 0;
#pragma unroll
        for (int g = 0; g < NGRP; g++)
            if (!((gsel >> g) & 1) && gsc[g] > best) { best = gsc[g]; bi = g; }
        gsel |= 1u << bi;
    }

    float t0 = ((gsel >> (lane >> 3)) & 1)       ? f0 : 0.f;
    float t1 = ((gsel >> (4 + (lane >> 3))) & 1) ? f1 : 0.f;

    int   myidx = 0;
    float myw = 0.f;
    float wsum = 0.f;
#pragma unroll
    for (int k = 0; k < TOPK; k++) {
        float v; int ix;
        if (t1 > t0) { v = t1; ix = lane + 32; } else { v = t0; ix = lane; }
#pragma unroll
        for (int off = 16; off; off >>= 1) {
            float ov = __shfl_xor_sync(FULL, v, off);
            int   oi = __shfl_xor_sync(FULL, ix, off);
            if (ov > v || (ov == v && oi < ix)) { v = ov; ix = oi; }
        }
        float wv = __shfl_sync(FULL, (ix < 32) ? s0 : s1, ix & 31);
        if (lane == k) { myidx = ix; myw = wv; }
        wsum += wv;
        if (lane == (ix & 31)) { if (ix < 32) t0 = -1e30f; else t1 = -1e30f; }
    }
    float inv = SCALE / (wsum + 1e-20f);
    if (lane < TOPK) {
        g_topk_idx[t * TOPK + lane] = myidx;
        g_topk_w[t * TOPK + lane] = myw * inv;
        atomicAdd(&g_counts[myidx], 1);
    }
}

__global__ void scan_kernel() {
    if (threadIdx.x == 0) {
        int run = 0;
        for (int e = 0; e < NEXP; e++) {
            int c = g_counts[e];
            int cc = c < CAPE ? c : CAPE;
            g_offsets[e] = run;
            g_ecount[e] = cc;
            run += cc;
        }
    }
}

__global__ void assign_kernel() {
    int s = blockIdx.x * blockDim.x + threadIdx.x;
    if (s >= SKTOT) return;
    int e = g_topk_idx[s];
    int p = atomicAdd(&g_fill[e], 1);
    if (p < CAPE) {
        int r = g_offsets[e] + p;
        g_row_token[r] = s / TOPK;
        g_row_weight[r] = g_topk_w[s];
    }
}

// =====================================================================
// Expert GEMM1
// =====================================================================
__global__ void __launch_bounds__(256, 2) eg1_kernel(const float* __restrict__ w1,
                                                     const float* __restrict__ w3) {
    extern __shared__ char sm[];
    const int tid = threadIdx.x, lane = tid & 31, wid = tid >> 5;
    const int wm = wid & 1, wn = wid >> 1;
    const int e  = blockIdx.z;
    const int me = g_ecount[e];
    const int m0 = blockIdx.y * 128;
    if (m0 >= me) return;
    const int f0 = blockIdx.x * 64;
    const int roff = g_offsets[e];
    const uint32_t smb = smem_u32(sm);

    int* toks = (int*)sm;
    if (tid < 128) {
        int m = m0 + tid;
        toks[tid] = g_row_token[roff + ((m < me) ? m : 0)];
    }
    __syncthreads();

    const int lr = tid >> 1, kseg = (tid & 1) * 16;
    const uint32_t soff = (uint32_t)(lr * STRIDE + kseg * 2);
    const __half* axh = g_x_h + (size_t)toks[lr] * HDIM + kseg;
    const __half* axl = g_x_l + (size_t)toks[lr] * HDIM + kseg;
    const float* bp = ((lr & 1) ? w3 : w1) + ((size_t)e * FDIM + f0 + (lr >> 1)) * HDIM + kseg;

    float acc[4][4][4];
#pragma unroll
    for (int i = 0; i < 4; i++)
#pragma unroll
        for (int j = 0; j < 4; j++)
#pragma unroll
            for (int k = 0; k < 4; k++) acc[i][j][k] = 0.f;

    cp32B(smb + toff3(0, 0) + soff, axh);
    cp32B(smb + toff3(0, 1) + soff, axl);
    {
        float rb[16];
        ldg16f(rb, bp);
        sts_h16(sm + toff3(0, 2) + soff, rb);
    }
    CP_COMMIT();
    float rbn[16];
    ldg16f(rbn, bp + 32);

    int buf = 0;
    const int NCH = HDIM / 32;
    for (int ch = 0; ch < NCH; ch++) {
        if (ch + 1 < NCH) {
            int k0 = (ch + 1) * 32;
            cp32B(smb + toff3(buf ^ 1, 0) + soff, axh + k0);
            cp32B(smb + toff3(buf ^ 1, 1) + soff, axl + k0);
            sts_h16(sm + toff3(buf ^ 1, 2) + soff, rbn);
            CP_COMMIT(); CP_WAIT1();
            if (ch + 2 < NCH) ldg16f(rbn, bp + (ch + 2) * 32);
        } else CP_WAIT0();
        __syncthreads();
        mma_tile2(acc, smb, buf, wm, wn, lane);
        __syncthreads();
        buf ^= 1;
    }

#pragma unroll
    for (int mi = 0; mi < 4; mi++) {
        int r = m0 + wm * 64 + mi * 16 + (lane >> 2);
#pragma unroll
        for (int ni = 0; ni < 4; ni++) {
            int lc = f0 + wn * 16 + ni * 4 + (lane & 3);
            float* d = acc[mi][ni];
            if (r < me)
                g_hb_h[(size_t)(roff + r) * FDIM + lc] = __float2half_rn(silu_mul(d[0], d[1]));
            if (r + 8 < me)
                g_hb_h[(size_t)(roff + r + 8) * FDIM + lc] = __float2half_rn(silu_mul(d[2], d[3]));
        }
    }
}

// =====================================================================
// Expert GEMM2
// =====================================================================
__global__ void __launch_bounds__(256, 2) eg2_kernel(const float* __restrict__ w2,
                                                     float* __restrict__ out) {
    extern __shared__ char sm[];
    const int tid = threadIdx.x, lane = tid & 31, wid = tid >> 5;
    const int wm = wid & 1, wn = wid >> 1;
    const int e  = blockIdx.z;
    const int me = g_ecount[e];
    const int m0 = blockIdx.y * 128;
    if (m0 >= me) return;
    const int n0 = blockIdx.x * 128;
    const int roff = g_offsets[e];
    const uint32_t smb = smem_u32(sm);

    int*   toks = (int*)sm;
    float* wro  = (float*)(sm + 512);
    if (tid < 128) {
        int m = m0 + tid;
        bool v = m < me;
        toks[tid] = v ? g_row_token[roff + m] : 0;
        wro[tid]  = v ? g_row_weight[roff + m] : 0.f;
    }
    __syncthreads();

    const int lr = tid >> 1, kseg = (tid & 1) * 16;
    const uint32_t soff = (uint32_t)(lr * STRIDE + kseg * 2);
    int mm = m0 + lr;
    size_t arow = (size_t)(roff + ((mm < me) ? mm : (me - 1)));
    const __half* axh = g_hb_h + arow * FDIM + kseg;
    const float* bp = w2 + ((size_t)e * HDIM + n0 + lr) * FDIM + kseg;

    float acc[4][4][4];
#pragma unroll
    for (int i = 0; i < 4; i++)
#pragma unroll
        for (int j = 0; j < 4; j++)
#pragma unroll
            for (int k = 0; k < 4; k++) acc[i][j][k] = 0.f;

    cp32B(smb + toff2(0, 0) + soff, axh);
    {
        float rb[16];
        ldg16f(rb, bp);
        sts_h16(sm + toff2(0, 1) + soff, rb);
    }
    CP_COMMIT();
    float rbn[16];
    ldg16f(rbn, bp + 32);

    int buf = 0;
    const int NCH = FDIM / 32;
    for (int ch = 0; ch < NCH; ch++) {
        if (ch + 1 < NCH) {
            int k0 = (ch + 1) * 32;
            cp32B(smb + toff2(buf ^ 1, 0) + soff, axh + k0);
            sts_h16(sm + toff2(buf ^ 1, 1) + soff, rbn);
            CP_COMMIT(); CP_WAIT1();
            if (ch + 2 < NCH) ldg16f(rbn, bp + (ch + 2) * 32);
        } else CP_WAIT0();
        __syncthreads();
        mma_tile1(acc, smb, buf, wm, wn, lane);
        __syncthreads();
        buf ^= 1;
    }

#pragma unroll
    for (int mi = 0; mi < 4; mi++) {
        int lrow = wm * 64 + mi * 16 + (lane >> 2);
        int r = m0 + lrow;
        int t0 = toks[lrow], t1 = toks[lrow + 8];
        float w0 = wro[lrow], w1v = wro[lrow + 8];
#pragma unroll
        for (int ni = 0; ni < 4; ni++) {
            int col = n0 + wn * 32 + ni * 8 + 2 * (lane & 3);
            float* d = acc[mi][ni];
            if (r < me) {
                atomicAdd(out + (size_t)t0 * HDIM + col,     d[0] * w0);
                atomicAdd(out + (size_t)t0 * HDIM + col + 1, d[1] * w0);
            }
            if (r + 8 < me) {
                atomicAdd(out + (size_t)t1 * HDIM + col,     d[2] * w1v);
                atomicAdd(out + (size_t)t1 * HDIM + col + 1, d[3] * w1v);
            }
        }
    }
}

// =====================================================================
// Shared GEMM1
// =====================================================================
__global__ void __launch_bounds__(256, 2) sg1_kernel() {
    extern __shared__ char sm[];
    const int tid = threadIdx.x, lane = tid & 31, wid = tid >> 5;
    const int wm = wid & 1, wn = wid >> 1;
    const int m0 = blockIdx.y * 128;
    const int f0 = blockIdx.x * 64;
    const uint32_t smb = smem_u32(sm);

    const int lr = tid >> 1, kseg = (tid & 1) * 16;
    const uint32_t soff = (uint32_t)(lr * STRIDE + kseg * 2);
    const __half* axh = g_x_h + (size_t)(m0 + lr) * HDIM + kseg;
    const __half* axl = g_x_l + (size_t)(m0 + lr) * HDIM + kseg;
    const __half* bxh = ((lr & 1) ? g_su_h : g_sg_h) + (size_t)(f0 + (lr >> 1)) * HDIM + kseg;

    float acc[4][4][4];
#pragma unroll
    for (int i = 0; i < 4; i++)
#pragma unroll
        for (int j = 0; j < 4; j++)
#pragma unroll
            for (int k = 0; k < 4; k++) acc[i][j][k] = 0.f;

    cp32B(smb + toff3(0, 0) + soff, axh);
    cp32B(smb + toff3(0, 1) + soff, axl);
    cp32B(smb + toff3(0, 2) + soff, bxh);
    CP_COMMIT();

    int buf = 0;
    const int NCH = HDIM / 32;
    for (int ch = 0; ch < NCH; ch++) {
        if (ch + 1 < NCH) {
            int k0 = (ch + 1) * 32;
            cp32B(smb + toff3(buf ^ 1, 0) + soff, axh + k0);
            cp32B(smb + toff3(buf ^ 1, 1) + soff, axl + k0);
            cp32B(smb + toff3(buf ^ 1, 2) + soff, bxh + k0);
            CP_COMMIT(); CP_WAIT1();
        } else CP_WAIT0();
        __syncthreads();
        mma_tile2(acc, smb, buf, wm, wn, lane);
        __syncthreads();
        buf ^= 1;
    }

#pragma unroll
    for (int mi = 0; mi < 4; mi++) {
        int r = m0 + wm * 64 + mi * 16 + (lane >> 2);
#pragma unroll
        for (int ni = 0; ni < 4; ni++) {
            int lc = f0 + wn * 16 + ni * 4 + (lane & 3);
            float* d = acc[mi][ni];
            g_hs_h[(size_t)r * F2DIM + lc]       = __float2half_rn(silu_mul(d[0], d[1]));
            g_hs_h[(size_t)(r + 8) * F2DIM + lc] = __float2half_rn(silu_mul(d[2], d[3]));
        }
    }
}

// =====================================================================
// Shared GEMM2
// =====================================================================
__global__ void __launch_bounds__(256, 2) sg2_kernel(float* __restrict__ out) {
    extern __shared__ char sm[];
    const int tid = threadIdx.x, lane = tid & 31, wid = tid >> 5;
    const int wm = wid & 1, wn = wid >> 1;
    const int m0 = blockIdx.y * 128;
    const int n0 = blockIdx.x * 128;
    const uint32_t smb = smem_u32(sm);

    const int lr = tid >> 1, kseg = (tid & 1) * 16;
    const uint32_t soff = (uint32_t)(lr * STRIDE + kseg * 2);
    const __half* axh = g_hs_h + (size_t)(m0 + lr) * F2DIM + kseg;
    const __half* bxh = g_sd_h + (size_t)(n0 + lr) * F2DIM + kseg;

    float acc[4][4][4];
#pragma unroll
    for (int i = 0; i < 4; i++)
#pragma unroll
        for (int j = 0; j < 4; j++)
#pragma unroll
            for (int k = 0; k < 4; k++) acc[i][j][k] = 0.f;

    cp32B(smb + toff2(0, 0) + soff, axh);
    cp32B(smb + toff2(0, 1) + soff, bxh);
    CP_COMMIT();

    int buf = 0;
    const int NCH = F2DIM / 32;
    for (int ch = 0; ch < NCH; ch++) {
        if (ch + 1 < NCH) {
            int k0 = (ch + 1) * 32;
            cp32B(smb + toff2(buf ^ 1, 0) + soff, axh + k0);
            cp32B(smb + toff2(buf ^ 1, 1) + soff, bxh + k0);
            CP_COMMIT(); CP_WAIT1();
        } else CP_WAIT0();
        __syncthreads();
        mma_tile1(acc, smb, buf, wm, wn, lane);
        __syncthreads();
        buf ^= 1;
    }

#pragma unroll
    for (int mi = 0; mi < 4; mi++) {
        int r = m0 + wm * 64 + mi * 16 + (lane >> 2);
#pragma unroll
        for (int ni = 0; ni < 4; ni++) {
            int col = n0 + wn * 32 + ni * 8 + 2 * (lane & 3);
            float* d = acc[mi][ni];
            *(float2*)(out + (size_t)r * HDIM + col)       = make_float2(d[0], d[1]);
            *(float2*)(out + (size_t)(r + 8) * HDIM + col) = make_float2(d[2], d[3]);
        }
    }
}

// ---------------- launch ----------------
extern "C" void kernel_launch(void* const* d_in, const int* in_sizes, int n_in,
                              void* d_out, int out_size) {
    const float* x   = (const float*)d_in[0];
    const float* gw  = (const float*)d_in[1];
    const float* eb  = (const float*)d_in[2];
    const float* w1  = (const float*)d_in[3];
    const float* w2  = (const float*)d_in[4];
    const float* w3  = (const float*)d_in[5];
    const float* sg  = (const float*)d_in[6];
    const float* su  = (const float*)d_in[7];
    const float* sd  = (const float*)d_in[8];
    float* out = (float*)d_out;

    static bool init_done = false;
    static __half *pxh, *pxl, *pgwh, *pgwl, *psgh, *psuh, *psdh;
    if (!init_done) {
        cudaFuncSetAttribute(eg1_kernel, cudaFuncAttributeMaxDynamicSharedMemorySize, SMEM_SZ3);
        cudaFuncSetAttribute(sg1_kernel, cudaFuncAttributeMaxDynamicSharedMemorySize, SMEM_SZ3);
        cudaFuncSetAttribute(logits_kernel, cudaFuncAttributeMaxDynamicSharedMemorySize, SMEM_SZ3);
        cudaFuncSetAttribute(eg2_kernel, cudaFuncAttributeMaxDynamicSharedMemorySize, SMEM_SZ2);
        cudaFuncSetAttribute(sg2_kernel, cudaFuncAttributeMaxDynamicSharedMemorySize, SMEM_SZ2);
        cudaGetSymbolAddress((void**)&pxh,  g_x_h);  cudaGetSymbolAddress((void**)&pxl, g_x_l);
        cudaGetSymbolAddress((void**)&pgwh, g_gw_h); cudaGetSymbolAddress((void**)&pgwl, g_gw_l);
        cudaGetSymbolAddress((void**)&psgh, g_sg_h); cudaGetSymbolAddress((void**)&psuh, g_su_h);
        cudaGetSymbolAddress((void**)&psdh, g_sd_h);
        init_done = true;
    }

    // presplit
    split2_kernel<<<TOK * HDIM / 8 / 256, 256>>>(x, pxh, pxl);
    split2_kernel<<<NEXP * HDIM / 8 / 256, 256>>>(gw, pgwh, pgwl);
    split1x3_kernel<<<dim3(F2DIM * HDIM / 8 / 256, 3), 256>>>(sg, su, sd, psgh, psuh, psdh);

    init_kernel<<<1, 64>>>();
    logits_kernel<<<TOK / 128, 256, SMEM_SZ3>>>();
    topk_kernel<<<TOK / 8, 256>>>(eb);
    scan_kernel<<<1, 32>>>();
    assign_kernel<<<SKTOT / 256, 256>>>();

    // expert up-proj + SwiGLU -> hbuf plane
    eg1_kernel<<<dim3(FDIM / 64, CAPE / 128, NEXP), 256, SMEM_SZ3>>>(w1, w3);

    // shared expert: sg1 -> hs plane, sg2 overwrites out
    sg1_kernel<<<dim3(F2DIM / 64, TOK / 128), 256, SMEM_SZ3>>>();
    sg2_kernel<<<dim3(HDIM / 128, TOK / 128), 256, SMEM_SZ2>>>(out);

    // expert down-proj + weighted scatter-add
    eg2_kernel<<<dim3(HDIM / 128, CAPE / 128, NEXP), 256, SMEM_SZ2>>>(w2, out);
}

// round 10
// speedup vs baseline: 2.1642x; 1.2794x over previous
#include <cuda_runtime.h>
#include <cuda_fp16.h>
#include <math.h>
#include <stdint.h>

// ---------------- problem constants ----------------
#define TOK     2048
#define HDIM    1024
#define FDIM    512
#define F2DIM   1024
#define NEXP    64
#define TOPK    8
#define NGRP    8
#define TGRP    4
#define CAPE    1024
#define SKTOT   (TOK*TOPK)
#define SCALE   2.5f

// ---------------- device scratch ----------------
__device__ __half g_x_h[TOK * HDIM];
__device__ __half g_x_l[TOK * HDIM];      // used only by logits (routing precision)
__device__ __half g_gw_h[NEXP * HDIM];
__device__ __half g_gw_l[NEXP * HDIM];
__device__ __half g_sg_h[F2DIM * HDIM];
__device__ __half g_su_h[F2DIM * HDIM];
__device__ __half g_sd_h[HDIM * F2DIM];
__device__ __half g_hb_h[SKTOT * FDIM];
__device__ __half g_hs_h[TOK * F2DIM];
__device__ float g_logits[TOK * NEXP];
__device__ int   g_topk_idx[SKTOT];
__device__ float g_topk_w[SKTOT];
__device__ int   g_counts[NEXP];
__device__ int   g_fill[NEXP];
__device__ int   g_offsets[NEXP];
__device__ int   g_ecount[NEXP];
__device__ int   g_row_token[SKTOT];
__device__ float g_row_weight[SKTOT];

// ---------------- helpers ----------------
__device__ __forceinline__ float silu_mul(float g, float u) {
    return g / (1.f + expf(-g)) * u;
}
__device__ __forceinline__ uint32_t smem_u32(const void* p) {
    uint32_t a;
    asm("{ .reg .u64 t; cvta.to.shared.u64 t, %1; cvt.u32.u64 %0, t; }" : "=r"(a) : "l"(p));
    return a;
}
__device__ __forceinline__ uint32_t h_pair(float a, float b) {
    uint32_t r;
    asm("cvt.rn.f16x2.f32 %0, %1, %2;" : "=r"(r) : "f"(b), "f"(a));
    return r;
}

// ---------------- mma.sync / ldmatrix / cp.async primitives ----------------
__device__ __forceinline__ void ldsm4(uint32_t* r, uint32_t a) {
    asm volatile("ldmatrix.sync.aligned.m8n8.x4.shared.b16 {%0,%1,%2,%3}, [%4];"
                 : "=r"(r[0]), "=r"(r[1]), "=r"(r[2]), "=r"(r[3]) : "r"(a));
}
__device__ __forceinline__ void mma_f16(float* d, const uint32_t* a, const uint32_t* b) {
    asm volatile("mma.sync.aligned.m16n8k16.row.col.f32.f16.f16.f32 "
                 "{%0,%1,%2,%3}, {%4,%5,%6,%7}, {%8,%9}, {%0,%1,%2,%3};"
                 : "+f"(d[0]), "+f"(d[1]), "+f"(d[2]), "+f"(d[3])
                 : "r"(a[0]), "r"(a[1]), "r"(a[2]), "r"(a[3]), "r"(b[0]), "r"(b[1]));
}
#define CP16(dst, src) \
    asm volatile("cp.async.cg.shared.global [%0], [%1], 16;" :: "r"(dst), "l"(src))
#define CP_COMMIT() asm volatile("cp.async.commit_group;" ::: "memory")
#define CP_WAIT1()  asm volatile("cp.async.wait_group 1;" ::: "memory")
#define CP_WAIT0()  asm volatile("cp.async.wait_group 0;" ::: "memory")

// ---------------- SMEM tile layout ----------------
#define STRIDE   80
#define PLANE    10240
#define SM_TILES 1024
#define SMEM_SZ3 (SM_TILES + 6 * PLANE)   // 62464 : logits kernel only
#define SMEM_SZ2 (SM_TILES + 4 * PLANE)   // 41984 : all four main GEMMs

__device__ __forceinline__ uint32_t toff2(int buf, int p) {
    return SM_TILES + (uint32_t)(buf * 2 + p) * PLANE;
}

// 1-product chunk: acc += A*B   (planes: 0=A 1=B)
__device__ __forceinline__ void mma_tile1(float (&acc)[4][4][4], uint32_t smb, int buf,
                                          int wm, int wn, int lane) {
    const uint32_t base = smb + SM_TILES + (uint32_t)buf * 2 * PLANE;
    const uint32_t la = base + (uint32_t)((wm * 64 + (lane & 15)) * STRIDE) + (uint32_t)((lane >> 4) << 4);
    const uint32_t lb = base + PLANE + ((lane & 16) ? 8 * STRIDE : 0)
                        + (uint32_t)((wn * 32 + (lane & 7)) * STRIDE)
                        + (uint32_t)(((lane >> 3) & 1) << 4);
#pragma unroll
    for (int ks = 0; ks < 2; ks++) {
        const int ko = ks * 32;
        uint32_t ah[4][4], bf[2][4];
#pragma unroll
        for (int mi = 0; mi < 4; mi++) ldsm4(ah[mi], la + mi * 16 * STRIDE + ko);
        ldsm4(bf[0], lb + ko);
        ldsm4(bf[1], lb + 16 * STRIDE + ko);
#pragma unroll
        for (int mi = 0; mi < 4; mi++)
#pragma unroll
            for (int ni = 0; ni < 4; ni++)
                mma_f16(acc[mi][ni], ah[mi], &bf[ni >> 1][(ni & 1) * 2]);
    }
}

// ---------------- loaders ----------------
__device__ __forceinline__ void ldg16f(float* r, const float* __restrict__ p) {
#pragma unroll
    for (int i = 0; i < 4; i++) *(float4*)(r + i * 4) = *(const float4*)(p + i * 4);
}
__device__ __forceinline__ void sts_h16(char* p, const float* v) {
    uint4 H0, H1;
    H0.x = h_pair(v[0], v[1]);   H0.y = h_pair(v[2], v[3]);
    H0.z = h_pair(v[4], v[5]);   H0.w = h_pair(v[6], v[7]);
    H1.x = h_pair(v[8], v[9]);   H1.y = h_pair(v[10], v[11]);
    H1.z = h_pair(v[12], v[13]); H1.w = h_pair(v[14], v[15]);
    *(uint4*)p = H0; *(uint4*)(p + 16) = H1;
}
__device__ __forceinline__ void cp32B(uint32_t d, const __half* s) {
    CP16(d, s); CP16(d + 16, s + 8);
}

// ---------------- presplit kernels ----------------
__global__ __launch_bounds__(256) void split2_kernel(const float* __restrict__ s,
                                                     __half* __restrict__ hq,
                                                     __half* __restrict__ lq) {
    int i = blockIdx.x * blockDim.x + threadIdx.x;
    const float4* p = (const float4*)s + (size_t)i * 2;
    float4 v0 = p[0], v1 = p[1];
    float vv[8] = {v0.x, v0.y, v0.z, v0.w, v1.x, v1.y, v1.z, v1.w};
    uint4 H, L;
    uint32_t* hp = (uint32_t*)&H;
    uint32_t* lp = (uint32_t*)&L;
#pragma unroll
    for (int j = 0; j < 4; j++) {
        __half2 h = __floats2half2_rn(vv[2 * j], vv[2 * j + 1]);
        float2 bk = __half22float2(h);
        __half2 l = __floats2half2_rn(vv[2 * j] - bk.x, vv[2 * j + 1] - bk.y);
        hp[j] = *(uint32_t*)&h;
        lp[j] = *(uint32_t*)&l;
    }
    ((uint4*)hq)[i] = H;
    ((uint4*)lq)[i] = L;
}
__global__ __launch_bounds__(256) void split1x3_kernel(const float* __restrict__ s0,
                                                       const float* __restrict__ s1,
                                                       const float* __restrict__ s2,
                                                       __half* __restrict__ h0,
                                                       __half* __restrict__ h1,
                                                       __half* __restrict__ h2) {
    int i = blockIdx.x * blockDim.x + threadIdx.x;
    const float* s = (blockIdx.y == 0) ? s0 : (blockIdx.y == 1) ? s1 : s2;
    __half* hq     = (blockIdx.y == 0) ? h0 : (blockIdx.y == 1) ? h1 : h2;
    const float4* p = (const float4*)s + (size_t)i * 2;
    float4 v0 = p[0], v1 = p[1];
    uint4 H;
    H.x = h_pair(v0.x, v0.y); H.y = h_pair(v0.z, v0.w);
    H.z = h_pair(v1.x, v1.y); H.w = h_pair(v1.z, v1.w);
    ((uint4*)hq)[i] = H;
}

// ---------------- init ----------------
__global__ void init_kernel() {
    int i = threadIdx.x;
    if (i < NEXP) { g_counts[i] = 0; g_fill[i] = 0; }
}

// =====================================================================
// logits: x planes @ gw planes (3-product, high precision for routing)
// =====================================================================
__global__ void __launch_bounds__(256, 2) logits_kernel() {
    extern __shared__ char sm[];
    const int tid = threadIdx.x, lane = tid & 31, wid = tid >> 5;
    const int wm = wid & 1, wn = wid >> 1;
    const int m0 = blockIdx.x * 128;
    const uint32_t smb = smem_u32(sm);

    const int lr = tid >> 1, kseg = (tid & 1) * 16;
    const uint32_t soffA = (uint32_t)(lr * STRIDE + kseg * 2);
    const __half* axh = g_x_h + (size_t)(m0 + lr) * HDIM + kseg;
    const __half* axl = g_x_l + (size_t)(m0 + lr) * HDIM + kseg;
    const int br = tid >> 2, bks = (tid & 3) * 8;
    const uint32_t soffB = (uint32_t)(br * STRIDE + bks * 2);
    const __half* bgh = g_gw_h + (size_t)br * HDIM + bks;
    const __half* bgl = g_gw_l + (size_t)br * HDIM + bks;

    auto bufb = [&](int buf) { return smb + SM_TILES + (uint32_t)buf * 30720u; };

    float acc[4][2][4];
#pragma unroll
    for (int i = 0; i < 4; i++)
#pragma unroll
        for (int j = 0; j < 2; j++)
#pragma unroll
            for (int k = 0; k < 4; k++) acc[i][j][k] = 0.f;

    cp32B(bufb(0) + soffA, axh);
    cp32B(bufb(0) + 10240 + soffA, axl);
    CP16(bufb(0) + 20480 + soffB, bgh);
    CP16(bufb(0) + 25600 + soffB, bgl);
    CP_COMMIT();

    int buf = 0;
    const int NCH = HDIM / 32;
    for (int ch = 0; ch < NCH; ch++) {
        if (ch + 1 < NCH) {
            int k0 = (ch + 1) * 32;
            cp32B(bufb(buf ^ 1) + soffA, axh + k0);
            cp32B(bufb(buf ^ 1) + 10240 + soffA, axl + k0);
            CP16(bufb(buf ^ 1) + 20480 + soffB, bgh + k0);
            CP16(bufb(buf ^ 1) + 25600 + soffB, bgl + k0);
            CP_COMMIT(); CP_WAIT1();
        } else CP_WAIT0();
        __syncthreads();
        {
            const uint32_t base = bufb(buf);
            const uint32_t la = base + (uint32_t)((wm * 64 + (lane & 15)) * STRIDE) + (uint32_t)((lane >> 4) << 4);
            const uint32_t lb = base + 20480 + ((lane & 16) ? 8 * STRIDE : 0)
                                + (uint32_t)((wn * 16 + (lane & 7)) * STRIDE)
                                + (uint32_t)(((lane >> 3) & 1) << 4);
#pragma unroll
            for (int ks = 0; ks < 2; ks++) {
                const int ko = ks * 32;
                uint32_t ah[4][4], al_[4][4], bh[4], bl[4];
#pragma unroll
                for (int mi = 0; mi < 4; mi++) ldsm4(ah[mi], la + mi * 16 * STRIDE + ko);
#pragma unroll
                for (int mi = 0; mi < 4; mi++) ldsm4(al_[mi], la + 10240 + mi * 16 * STRIDE + ko);
                ldsm4(bh, lb + ko);
                ldsm4(bl, lb + 5120 + ko);
#pragma unroll
                for (int mi = 0; mi < 4; mi++)
#pragma unroll
                    for (int ni = 0; ni < 2; ni++) {
                        mma_f16(acc[mi][ni], ah[mi],  &bh[ni * 2]);
                        mma_f16(acc[mi][ni], al_[mi], &bh[ni * 2]);
                        mma_f16(acc[mi][ni], ah[mi],  &bl[ni * 2]);
                    }
            }
        }
        __syncthreads();
        buf ^= 1;
    }

#pragma unroll
    for (int mi = 0; mi < 4; mi++) {
        int r = m0 + wm * 64 + mi * 16 + (lane >> 2);
#pragma unroll
        for (int ni = 0; ni < 2; ni++) {
            int col = wn * 16 + ni * 8 + 2 * (lane & 3);
            float* d = acc[mi][ni];
            *(float2*)(g_logits + (size_t)r * NEXP + col)       = make_float2(d[0], d[1]);
            *(float2*)(g_logits + (size_t)(r + 8) * NEXP + col) = make_float2(d[2], d[3]);
        }
    }
}

// =====================================================================
// topk: one warp per token
// =====================================================================
__global__ __launch_bounds__(256) void topk_kernel(const float* __restrict__ eb) {
    const int lane = threadIdx.x & 31;
    const int t = blockIdx.x * 8 + (threadIdx.x >> 5);
    const unsigned FULL = 0xffffffffu;

    float l0 = g_logits[(size_t)t * NEXP + lane];
    float l1 = g_logits[(size_t)t * NEXP + 32 + lane];
    float s0 = 1.f / (1.f + expf(-l0));
    float s1 = 1.f / (1.f + expf(-l1));
    float f0 = s0 + eb[lane];
    float f1 = s1 + eb[lane + 32];

    float m1a = f0, m2a = -1e30f, m1b = f1, m2b = -1e30f;
#pragma unroll
    for (int off = 4; off; off >>= 1) {
        float o1 = __shfl_xor_sync(FULL, m1a, off), o2 = __shfl_xor_sync(FULL, m2a, off);
        if (o1 >= m1a) { m2a = fmaxf(m1a, o2); m1a = o1; } else m2a = fmaxf(m2a, o1);
        float p1 = __shfl_xor_sync(FULL, m1b, off), p2 = __shfl_xor_sync(FULL, m2b, off);
        if (p1 >= m1b) { m2b = fmaxf(m1b, p2); m1b = p1; } else m2b = fmaxf(m2b, p1);
    }
    float g2lo = m1a + m2a;
    float g2hi = m1b + m2b;

    float gsc[NGRP];
#pragma unroll
    for (int g = 0; g < 4; g++) gsc[g]     = __shfl_sync(FULL, g2lo, g * 8);
#pragma unroll
    for (int g = 0; g < 4; g++) gsc[4 + g] = __shfl_sync(FULL, g2hi, g * 8);

    unsigned gsel = 0;
#pragma unroll
    for (int it = 0; it < TGRP; it++) {
        float best = -1e30f; int bi = 0;
#pragma unroll
        for (int g = 0; g < NGRP; g++)
            if (!((gsel >> g) & 1) && gsc[g] > best) { best = gsc[g]; bi = g; }
        gsel |= 1u << bi;
    }

    float t0 = ((gsel >> (lane >> 3)) & 1)       ? f0 : 0.f;
    float t1 = ((gsel >> (4 + (lane >> 3))) & 1) ? f1 : 0.f;

    int   myidx = 0;
    float myw = 0.f;
    float wsum = 0.f;
#pragma unroll
    for (int k = 0; k < TOPK; k++) {
        float v; int ix;
        if (t1 > t0) { v = t1; ix = lane + 32; } else { v = t0; ix = lane; }
#pragma unroll
        for (int off = 16; off; off >>= 1) {
            float ov = __shfl_xor_sync(FULL, v, off);
            int   oi = __shfl_xor_sync(FULL, ix, off);
            if (ov > v || (ov == v && oi < ix)) { v = ov; ix = oi; }
        }
        float wv = __shfl_sync(FULL, (ix < 32) ? s0 : s1, ix & 31);
        if (lane == k) { myidx = ix; myw = wv; }
        wsum += wv;
        if (lane == (ix & 31)) { if (ix < 32) t0 = -1e30f; else t1 = -1e30f; }
    }
    float inv = SCALE / (wsum + 1e-20f);
    if (lane < TOPK) {
        g_topk_idx[t * TOPK + lane] = myidx;
        g_topk_w[t * TOPK + lane] = myw * inv;
        atomicAdd(&g_counts[myidx], 1);
    }
}

__global__ void scan_kernel() {
    if (threadIdx.x == 0) {
        int run = 0;
        for (int e = 0; e < NEXP; e++) {
            int c = g_counts[e];
            int cc = c < CAPE ? c : CAPE;
            g_offsets[e] = run;
            g_ecount[e] = cc;
            run += cc;
        }
    }
}

__global__ void assign_kernel() {
    int s = blockIdx.x * blockDim.x + threadIdx.x;
    if (s >= SKTOT) return;
    int e = g_topk_idx[s];
    int p = atomicAdd(&g_fill[e], 1);
    if (p < CAPE) {
        int r = g_offsets[e] + p;
        g_row_token[r] = s / TOPK;
        g_row_weight[r] = g_topk_w[s];
    }
}

// =====================================================================
// Expert GEMM1: x (1 plane) @ interleaved(w1,w3) -> SwiGLU -> hbuf (1 plane)
// =====================================================================
__global__ void __launch_bounds__(256, 2) eg1_kernel(const float* __restrict__ w1,
                                                     const float* __restrict__ w3) {
    extern __shared__ char sm[];
    const int tid = threadIdx.x, lane = tid & 31, wid = tid >> 5;
    const int wm = wid & 1, wn = wid >> 1;
    const int e  = blockIdx.z;
    const int me = g_ecount[e];
    const int m0 = blockIdx.y * 128;
    if (m0 >= me) return;
    const int f0 = blockIdx.x * 64;
    const int roff = g_offsets[e];
    const uint32_t smb = smem_u32(sm);

    int* toks = (int*)sm;
    if (tid < 128) {
        int m = m0 + tid;
        toks[tid] = g_row_token[roff + ((m < me) ? m : 0)];
    }
    __syncthreads();

    const int lr = tid >> 1, kseg = (tid & 1) * 16;
    const uint32_t soff = (uint32_t)(lr * STRIDE + kseg * 2);
    const __half* axh = g_x_h + (size_t)toks[lr] * HDIM + kseg;
    const float* bp = ((lr & 1) ? w3 : w1) + ((size_t)e * FDIM + f0 + (lr >> 1)) * HDIM + kseg;

    float acc[4][4][4];
#pragma unroll
    for (int i = 0; i < 4; i++)
#pragma unroll
        for (int j = 0; j < 4; j++)
#pragma unroll
            for (int k = 0; k < 4; k++) acc[i][j][k] = 0.f;

    cp32B(smb + toff2(0, 0) + soff, axh);
    {
        float rb[16];
        ldg16f(rb, bp);
        sts_h16(sm + toff2(0, 1) + soff, rb);
    }
    CP_COMMIT();
    float rbn[16];
    ldg16f(rbn, bp + 32);

    int buf = 0;
    const int NCH = HDIM / 32;
    for (int ch = 0; ch < NCH; ch++) {
        if (ch + 1 < NCH) {
            int k0 = (ch + 1) * 32;
            cp32B(smb + toff2(buf ^ 1, 0) + soff, axh + k0);
            sts_h16(sm + toff2(buf ^ 1, 1) + soff, rbn);
            CP_COMMIT(); CP_WAIT1();
            if (ch + 2 < NCH) ldg16f(rbn, bp + (ch + 2) * 32);
        } else CP_WAIT0();
        __syncthreads();
        mma_tile1(acc, smb, buf, wm, wn, lane);
        __syncthreads();
        buf ^= 1;
    }

#pragma unroll
    for (int mi = 0; mi < 4; mi++) {
        int r = m0 + wm * 64 + mi * 16 + (lane >> 2);
#pragma unroll
        for (int ni = 0; ni < 4; ni++) {
            int lc = f0 + wn * 16 + ni * 4 + (lane & 3);
            float* d = acc[mi][ni];
            if (r < me)
                g_hb_h[(size_t)(roff + r) * FDIM + lc] = __float2half_rn(silu_mul(d[0], d[1]));
            if (r + 8 < me)
                g_hb_h[(size_t)(roff + r + 8) * FDIM + lc] = __float2half_rn(silu_mul(d[2], d[3]));
        }
    }
}

// =====================================================================
// Expert GEMM2: hbuf (1 plane) @ w2 -> weighted atomicAdd into out
// =====================================================================
__global__ void __launch_bounds__(256, 2) eg2_kernel(const float* __restrict__ w2,
                                                     float* __restrict__ out) {
    extern __shared__ char sm[];
    const int tid = threadIdx.x, lane = tid & 31, wid = tid >> 5;
    const int wm = wid & 1, wn = wid >> 1;
    const int e  = blockIdx.z;
    const int me = g_ecount[e];
    const int m0 = blockIdx.y * 128;
    if (m0 >= me) return;
    const int n0 = blockIdx.x * 128;
    const int roff = g_offsets[e];
    const uint32_t smb = smem_u32(sm);

    int*   toks = (int*)sm;
    float* wro  = (float*)(sm + 512);
    if (tid < 128) {
        int m = m0 + tid;
        bool v = m < me;
        toks[tid] = v ? g_row_token[roff + m] : 0;
        wro[tid]  = v ? g_row_weight[roff + m] : 0.f;
    }
    __syncthreads();

    const int lr = tid >> 1, kseg = (tid & 1) * 16;
    const uint32_t soff = (uint32_t)(lr * STRIDE + kseg * 2);
    int mm = m0 + lr;
    size_t arow = (size_t)(roff + ((mm < me) ? mm : (me - 1)));
    const __half* axh = g_hb_h + arow * FDIM + kseg;
    const float* bp = w2 + ((size_t)e * HDIM + n0 + lr) * FDIM + kseg;

    float acc[4][4][4];
#pragma unroll
    for (int i = 0; i < 4; i++)
#pragma unroll
        for (int j = 0; j < 4; j++)
#pragma unroll
            for (int k = 0; k < 4; k++) acc[i][j][k] = 0.f;

    cp32B(smb + toff2(0, 0) + soff, axh);
    {
        float rb[16];
        ldg16f(rb, bp);
        sts_h16(sm + toff2(0, 1) + soff, rb);
    }
    CP_COMMIT();
    float rbn[16];
    ldg16f(rbn, bp + 32);

    int buf = 0;
    const int NCH = FDIM / 32;
    for (int ch = 0; ch < NCH; ch++) {
        if (ch + 1 < NCH) {
            int k0 = (ch + 1) * 32;
            cp32B(smb + toff2(buf ^ 1, 0) + soff, axh + k0);
            sts_h16(sm + toff2(buf ^ 1, 1) + soff, rbn);
            CP_COMMIT(); CP_WAIT1();
            if (ch + 2 < NCH) ldg16f(rbn, bp + (ch + 2) * 32);
        } else CP_WAIT0();
        __syncthreads();
        mma_tile1(acc, smb, buf, wm, wn, lane);
        __syncthreads();
        buf ^= 1;
    }

#pragma unroll
    for (int mi = 0; mi < 4; mi++) {
        int lrow = wm * 64 + mi * 16 + (lane >> 2);
        int r = m0 + lrow;
        int t0 = toks[lrow], t1 = toks[lrow + 8];
        float w0 = wro[lrow], w1v = wro[lrow + 8];
#pragma unroll
        for (int ni = 0; ni < 4; ni++) {
            int col = n0 + wn * 32 + ni * 8 + 2 * (lane & 3);
            float* d = acc[mi][ni];
            if (r < me) {
                atomicAdd(out + (size_t)t0 * HDIM + col,     d[0] * w0);
                atomicAdd(out + (size_t)t0 * HDIM + col + 1, d[1] * w0);
            }
            if (r + 8 < me) {
                atomicAdd(out + (size_t)t1 * HDIM + col,     d[2] * w1v);
                atomicAdd(out + (size_t)t1 * HDIM + col + 1, d[3] * w1v);
            }
        }
    }
}

// =====================================================================
// Shared GEMM1: x (1 plane) @ interleaved(sg,su) plane -> SwiGLU -> hs
// =====================================================================
__global__ void __launch_bounds__(256, 2) sg1_kernel() {
    extern __shared__ char sm[];
    const int tid = threadIdx.x, lane = tid & 31, wid = tid >> 5;
    const int wm = wid & 1, wn = wid >> 1;
    const int m0 = blockIdx.y * 128;
    const int f0 = blockIdx.x * 64;
    const uint32_t smb = smem_u32(sm);

    const int lr = tid >> 1, kseg = (tid & 1) * 16;
    const uint32_t soff = (uint32_t)(lr * STRIDE + kseg * 2);
    const __half* axh = g_x_h + (size_t)(m0 + lr) * HDIM + kseg;
    const __half* bxh = ((lr & 1) ? g_su_h : g_sg_h) + (size_t)(f0 + (lr >> 1)) * HDIM + kseg;

    float acc[4][4][4];
#pragma unroll
    for (int i = 0; i < 4; i++)
#pragma unroll
        for (int j = 0; j < 4; j++)
#pragma unroll
            for (int k = 0; k < 4; k++) acc[i][j][k] = 0.f;

    cp32B(smb + toff2(0, 0) + soff, axh);
    cp32B(smb + toff2(0, 1) + soff, bxh);
    CP_COMMIT();

    int buf = 0;
    const int NCH = HDIM / 32;
    for (int ch = 0; ch < NCH; ch++) {
        if (ch + 1 < NCH) {
            int k0 = (ch + 1) * 32;
            cp32B(smb + toff2(buf ^ 1, 0) + soff, axh + k0);
            cp32B(smb + toff2(buf ^ 1, 1) + soff, bxh + k0);
            CP_COMMIT(); CP_WAIT1();
        } else CP_WAIT0();
        __syncthreads();
        mma_tile1(acc, smb, buf, wm, wn, lane);
        __syncthreads();
        buf ^= 1;
    }

#pragma unroll
    for (int mi = 0; mi < 4; mi++) {
        int r = m0 + wm * 64 + mi * 16 + (lane >> 2);
#pragma unroll
        for (int ni = 0; ni < 4; ni++) {
            int lc = f0 + wn * 16 + ni * 4 + (lane & 3);
            float* d = acc[mi][ni];
            g_hs_h[(size_t)r * F2DIM + lc]       = __float2half_rn(silu_mul(d[0], d[1]));
            g_hs_h[(size_t)(r + 8) * F2DIM + lc] = __float2half_rn(silu_mul(d[2], d[3]));
        }
    }
}

// =====================================================================
// Shared GEMM2: hs (1 plane) @ sd plane -> overwrite out
// =====================================================================
__global__ void __launch_bounds__(256, 2) sg2_kernel(float* __restrict__ out) {
    extern __shared__ char sm[];
    const int tid = threadIdx.x, lane = tid & 31, wid = tid >> 5;
    const int wm = wid & 1, wn = wid >> 1;
    const int m0 = blockIdx.y * 128;
    const int n0 = blockIdx.x * 128;
    const uint32_t smb = smem_u32(sm);

    const int lr = tid >> 1, kseg = (tid & 1) * 16;
    const uint32_t soff = (uint32_t)(lr * STRIDE + kseg * 2);
    const __half* axh = g_hs_h + (size_t)(m0 + lr) * F2DIM + kseg;
    const __half* bxh = g_sd_h + (size_t)(n0 + lr) * F2DIM + kseg;

    float acc[4][4][4];
#pragma unroll
    for (int i = 0; i < 4; i++)
#pragma unroll
        for (int j = 0; j < 4; j++)
#pragma unroll
            for (int k = 0; k < 4; k++) acc[i][j][k] = 0.f;

    cp32B(smb + toff2(0, 0) + soff, axh);
    cp32B(smb + toff2(0, 1) + soff, bxh);
    CP_COMMIT();

    int buf = 0;
    const int NCH = F2DIM / 32;
    for (int ch = 0; ch < NCH; ch++) {
        if (ch + 1 < NCH) {
            int k0 = (ch + 1) * 32;
            cp32B(smb + toff2(buf ^ 1, 0) + soff, axh + k0);
            cp32B(smb + toff2(buf ^ 1, 1) + soff, bxh + k0);
            CP_COMMIT(); CP_WAIT1();
        } else CP_WAIT0();
        __syncthreads();
        mma_tile1(acc, smb, buf, wm, wn, lane);
        __syncthreads();
        buf ^= 1;
    }

#pragma unroll
    for (int mi = 0; mi < 4; mi++) {
        int r = m0 + wm * 64 + mi * 16 + (lane >> 2);
#pragma unroll
        for (int ni = 0; ni < 4; ni++) {
            int col = n0 + wn * 32 + ni * 8 + 2 * (lane & 3);
            float* d = acc[mi][ni];
            *(float2*)(out + (size_t)r * HDIM + col)       = make_float2(d[0], d[1]);
            *(float2*)(out + (size_t)(r + 8) * HDIM + col) = make_float2(d[2], d[3]);
        }
    }
}

// ---------------- launch ----------------
extern "C" void kernel_launch(void* const* d_in, const int* in_sizes, int n_in,
                              void* d_out, int out_size) {
    const float* x   = (const float*)d_in[0];
    const float* gw  = (const float*)d_in[1];
    const float* eb  = (const float*)d_in[2];
    const float* w1  = (const float*)d_in[3];
    const float* w2  = (const float*)d_in[4];
    const float* w3  = (const float*)d_in[5];
    const float* sg  = (const float*)d_in[6];
    const float* su  = (const float*)d_in[7];
    const float* sd  = (const float*)d_in[8];
    float* out = (float*)d_out;

    static bool init_done = false;
    static __half *pxh, *pxl, *pgwh, *pgwl, *psgh, *psuh, *psdh;
    if (!init_done) {
        cudaFuncSetAttribute(logits_kernel, cudaFuncAttributeMaxDynamicSharedMemorySize, SMEM_SZ3);
        cudaFuncSetAttribute(eg1_kernel, cudaFuncAttributeMaxDynamicSharedMemorySize, SMEM_SZ2);
        cudaFuncSetAttribute(sg1_kernel, cudaFuncAttributeMaxDynamicSharedMemorySize, SMEM_SZ2);
        cudaFuncSetAttribute(eg2_kernel, cudaFuncAttributeMaxDynamicSharedMemorySize, SMEM_SZ2);
        cudaFuncSetAttribute(sg2_kernel, cudaFuncAttributeMaxDynamicSharedMemorySize, SMEM_SZ2);
        cudaGetSymbolAddress((void**)&pxh,  g_x_h);  cudaGetSymbolAddress((void**)&pxl, g_x_l);
        cudaGetSymbolAddress((void**)&pgwh, g_gw_h); cudaGetSymbolAddress((void**)&pgwl, g_gw_l);
        cudaGetSymbolAddress((void**)&psgh, g_sg_h); cudaGetSymbolAddress((void**)&psuh, g_su_h);
        cudaGetSymbolAddress((void**)&psdh, g_sd_h);
        init_done = true;
    }

    // presplit
    split2_kernel<<<TOK * HDIM / 8 / 256, 256>>>(x, pxh, pxl);
    split2_kernel<<<NEXP * HDIM / 8 / 256, 256>>>(gw, pgwh, pgwl);
    split1x3_kernel<<<dim3(F2DIM * HDIM / 8 / 256, 3), 256>>>(sg, su, sd, psgh, psuh, psdh);

    init_kernel<<<1, 64>>>();
    logits_kernel<<<TOK / 128, 256, SMEM_SZ3>>>();
    topk_kernel<<<TOK / 8, 256>>>(eb);
    scan_kernel<<<1, 32>>>();
    assign_kernel<<<SKTOT / 256, 256>>>();

    // expert up-proj + SwiGLU -> hbuf plane
    eg1_kernel<<<dim3(FDIM / 64, CAPE / 128, NEXP), 256, SMEM_SZ2>>>(w1, w3);

    // shared expert: sg1 -> hs plane, sg2 overwrites out
    sg1_kernel<<<dim3(F2DIM / 64, TOK / 128), 256, SMEM_SZ2>>>();
    sg2_kernel<<<dim3(HDIM / 128, TOK / 128), 256, SMEM_SZ2>>>(out);

    // expert down-proj + weighted scatter-add
    eg2_kernel<<<dim3(HDIM / 128, CAPE / 128, NEXP), 256, SMEM_SZ2>>>(w2, out);
}